// round 14
// baseline (speedup 1.0000x reference)
#include <cuda_runtime.h>
#include <cuda_fp16.h>
#include <math.h>
#include <stdint.h>

#define BATCH   2
#define SEQ     2048
#define DIM     2048
#define D_INNER 4096
#define D_STATE 128
#define N_HEADS 32
#define HEADDIM 128
#define D_CONV  4
#define CHUNK   256
#define NCHUNK  (SEQ/CHUNK)                       /* 8  */
#define NBCH    (BATCH*NCHUNK*N_HEADS)            /* 512 */
#define CONV_DIM (D_INNER + 2*D_STATE)            /* 4352 */
#define D_IN_PROJ (2*D_INNER + 2*D_STATE + N_HEADS) /* 8480 */
#define EPS 1e-5f

// ---------------- scratch (device globals, no allocation) ----------------
__device__ float g_zxbcdt[(size_t)BATCH*SEQ*D_IN_PROJ];
__device__ float g_xBC  [(size_t)BATCH*SEQ*CONV_DIM];
__device__ float g_dt   [(size_t)BATCH*SEQ*N_HEADS];
__device__ float g_dAcum[(size_t)BATCH*N_HEADS*SEQ];
__device__ __half g_G   [(size_t)BATCH*NCHUNK*CHUNK*CHUNK];     // fp16 now
__device__ float g_states[(size_t)NBCH*HEADDIM*D_STATE];
__device__ float g_y    [(size_t)BATCH*SEQ*D_INNER];
// fp16 operand mirrors
__device__ __half g_in_h  [(size_t)BATCH*SEQ*DIM];
__device__ __half g_win_h [(size_t)D_IN_PROJ*DIM];
__device__ __half g_wout_h[(size_t)DIM*D_INNER];
__device__ __half g_y_h   [(size_t)BATCH*SEQ*D_INNER];
__device__ __half g_bc_h  [(size_t)BATCH*SEQ*2*D_STATE];
// fp16 scan operands
__device__ __half g_xdt_h [(size_t)BATCH*SEQ*D_INNER];
__device__ __half g_LG    [(size_t)NBCH*CHUNK*CHUNK];
__device__ __half g_Bdec  [(size_t)NBCH*CHUNK*D_STATE];
__device__ __half g_Cexp  [(size_t)NBCH*CHUNK*D_STATE];
__device__ __half g_sin_h [(size_t)NBCH*HEADDIM*D_STATE];

__device__ __forceinline__ void cp16(uint32_t dst, const void* src, bool pred) {
    asm volatile("cp.async.cg.shared.global [%0], [%1], 16, %2;"
                 :: "r"(dst), "l"(src), "r"(pred ? 16 : 0));
}
__device__ __forceinline__ void ldsm4(uint32_t* r, uint32_t addr) {
    asm volatile("ldmatrix.sync.aligned.m8n8.x4.shared.b16 {%0,%1,%2,%3}, [%4];"
        : "=r"(r[0]), "=r"(r[1]), "=r"(r[2]), "=r"(r[3]) : "r"(addr));
}
// fast exp on FMA pipe: exp(x) for x<=0
__device__ __forceinline__ float fexp(float x) {
    float t = x * 1.4426950408889634f;
    t = fmaxf(t, -25.f);
    float fi = floorf(t);
    float f = t - fi;
    float p = 1.f + f*(0.69314718f + f*(0.24022651f + f*(0.05550411f
            + f*(0.00961813f + f*0.00133336f))));
    return p * __int_as_float(((int)fi + 127) << 23);
}

#define MMA16(acc, af, bf)                                                   \
    asm volatile(                                                            \
        "mma.sync.aligned.m16n8k16.row.col.f32.f16.f16.f32 "                 \
        "{%0,%1,%2,%3}, {%4,%5,%6,%7}, {%8,%9}, {%0,%1,%2,%3};"              \
        : "+f"(acc[0]), "+f"(acc[1]), "+f"(acc[2]), "+f"(acc[3])             \
        : "r"(af[0]), "r"(af[1]), "r"(af[2]), "r"(af[3]),                    \
          "r"(bf[0]), "r"(bf[1]))

// ================== fp16 mma.sync batched NT GEMM (projections) ===========
// BK=64, 3-stage cp.async, XOR-swizzled smem, ldmatrix. Output fp32 or fp16.
#define GSTG (128*64*2)
#define GSMEM (6*GSTG)
template<typename OutT>
__global__ __launch_bounds__(256, 2)
void gemm_h(const __half* __restrict__ A, long lda, long sA,
            const __half* __restrict__ W, long ldb, long sB,
            OutT* __restrict__ C, long ldc, long sC,
            int M, int N, int K, const float* __restrict__ bias)
{
    extern __shared__ char smem[];
    int bz = blockIdx.z;
    const __half* Ab = A + (long)bz * sA;
    const __half* Wb = W + (long)bz * sB;
    OutT*         Cb = C + (long)bz * sC;
    int bm = blockIdx.y * 128, bn = blockIdx.x * 128;
    int tid  = threadIdx.x;
    int warp = tid >> 5, lane = tid & 31;
    int wm = warp >> 2, wn = warp & 3;
    int g  = lane >> 2, t4 = lane & 3;

    uint32_t sAu = (uint32_t)__cvta_generic_to_shared(smem);
    uint32_t sBu = sAu + 3*GSTG;

    int arow = lane & 15;
    int achk = lane >> 4;
    int brow = ((lane >> 4) << 3) + (lane & 7);
    int bchk = (lane >> 3) & 1;

    float acc[4][4][4];
    #pragma unroll
    for (int i = 0; i < 4; i++)
        #pragma unroll
        for (int j = 0; j < 4; j++)
            #pragma unroll
            for (int q = 0; q < 4; q++) acc[i][j][q] = 0.f;

    const int KT = K / 64;

    #define LOADTILE(st, k0)                                                  \
    do {                                                                      \
        _Pragma("unroll")                                                     \
        for (int it = 0; it < 4; it++) {                                      \
            int idx = tid + it*256;                                           \
            int row = idx >> 3, c8 = idx & 7;                                 \
            int sc = c8 ^ (row & 7);                                          \
            cp16(sAu + (st)*GSTG + row*128 + sc*16,                           \
                 &Ab[(long)(bm+row)*lda + (k0) + c8*8], true);                \
        }                                                                     \
        _Pragma("unroll")                                                     \
        for (int it = 0; it < 4; it++) {                                      \
            int idx = tid + it*256;                                           \
            int row = idx >> 3, c8 = idx & 7;                                 \
            int sc = c8 ^ (row & 7);                                          \
            int gn = bn + row; bool p = gn < N;                               \
            cp16(sBu + (st)*GSTG + row*128 + sc*16,                           \
                 &Wb[(long)(p ? gn : 0)*ldb + (k0) + c8*8], p);               \
        }                                                                     \
    } while (0)

    LOADTILE(0, 0);
    asm volatile("cp.async.commit_group;");
    if (KT > 1) LOADTILE(1, 64);
    asm volatile("cp.async.commit_group;");

    for (int kt = 0; kt < KT; kt++) {
        asm volatile("cp.async.wait_group 1;" ::: "memory");
        __syncthreads();
        if (kt + 2 < KT) LOADTILE((kt+2) % 3, (kt+2)*64);
        asm volatile("cp.async.commit_group;");

        int st = kt % 3;
        #pragma unroll
        for (int ks = 0; ks < 4; ks++) {
            uint32_t af[4][4], bf[4][2];
            #pragma unroll
            for (int mt = 0; mt < 4; mt++) {
                int r = wm*64 + mt*16 + arow;
                int chk = (ks*2 + achk) ^ (r & 7);
                ldsm4(af[mt], sAu + st*GSTG + r*128 + chk*16);
            }
            #pragma unroll
            for (int np = 0; np < 2; np++) {
                int r = wn*32 + np*16 + brow;
                int chk = (ks*2 + bchk) ^ (r & 7);
                uint32_t t[4];
                ldsm4(t, sBu + st*GSTG + r*128 + chk*16);
                bf[np*2  ][0] = t[0]; bf[np*2  ][1] = t[1];
                bf[np*2+1][0] = t[2]; bf[np*2+1][1] = t[3];
            }
            #pragma unroll
            for (int mt = 0; mt < 4; mt++)
                #pragma unroll
                for (int nt = 0; nt < 4; nt++)
                    MMA16(acc[mt][nt], af[mt], bf[nt]);
        }
        __syncthreads();
    }
    #undef LOADTILE

    #pragma unroll
    for (int mt = 0; mt < 4; mt++) {
        int row0 = bm + wm*64 + mt*16 + g;
        #pragma unroll
        for (int nt = 0; nt < 4; nt++) {
            int col0 = bn + wn*32 + nt*8 + 2*t4;
            #pragma unroll
            for (int q = 0; q < 2; q++) {
                int col = col0 + q;
                if (col < N) {
                    float b0 = bias ? bias[col] : 0.f;
                    float v0 = acc[mt][nt][q] + b0;
                    float v1 = acc[mt][nt][2+q] + b0;
                    if (sizeof(OutT) == 2) {
                        ((__half*)Cb)[(long)row0*ldc + col]     = __float2half_rn(v0);
                        ((__half*)Cb)[(long)(row0+8)*ldc + col] = __float2half_rn(v1);
                    } else {
                        ((float*)Cb)[(long)row0*ldc + col]     = v0;
                        ((float*)Cb)[(long)(row0+8)*ldc + col] = v1;
                    }
                }
            }
        }
    }
}

// =============== scan GEMMs: 128x128 tile, K-step 32, fp16 ================
#define SS 42

struct ZIdx { int b, c, h; };
__device__ __forceinline__ ZIdx zdec(int z) {
    ZIdx r; r.h = z % N_HEADS; int bc = z / N_HEADS;
    r.c = bc % NCHUNK; r.b = bc / NCHUNK; return r;
}

template<int STAGEA, int STAGEB, int OUTMODE>
__device__ __forceinline__ void scan_gemm_core(
    const __half* Ag, long lda,
    const __half* Bg, long ldb,
    float* Cg, long ldc,
    int KT)
{
    __shared__ __half As[128][SS];
    __shared__ __half Bs[128][SS];
    int tid = threadIdx.x;
    int warp = tid >> 5, lane = tid & 31;
    int wm = warp >> 2, wn = warp & 3;
    int g = lane >> 2, t4 = lane & 3;

    float acc[4][4][4];
    #pragma unroll
    for (int i = 0; i < 4; i++)
        #pragma unroll
        for (int j = 0; j < 4; j++)
            #pragma unroll
            for (int q = 0; q < 4; q++) acc[i][j][q] = 0.f;

    for (int kt = 0; kt < KT; kt++) {
        int k0 = kt * 32;
        if (STAGEA == 0) {
            #pragma unroll
            for (int i = 0; i < 8; i++) {
                int idx = tid + i*256;
                int row = idx >> 4, c2 = (idx & 15) * 2;
                *(__half2*)&As[row][c2] = *(const __half2*)&Ag[(long)row*lda + k0 + c2];
            }
        } else {
            #pragma unroll
            for (int i = 0; i < 8; i++) {
                int idx = tid + i*256;
                int k = idx >> 6, m2 = (idx & 63) * 2;
                __half2 v = *(const __half2*)&Ag[(long)(k0+k)*lda + m2];
                As[m2  ][k] = __low2half(v);
                As[m2+1][k] = __high2half(v);
            }
        }
        if (STAGEB == 0) {
            #pragma unroll
            for (int i = 0; i < 8; i++) {
                int idx = tid + i*256;
                int row = idx >> 4, c2 = (idx & 15) * 2;
                *(__half2*)&Bs[row][c2] = *(const __half2*)&Bg[(long)row*ldb + k0 + c2];
            }
        } else {
            #pragma unroll
            for (int i = 0; i < 8; i++) {
                int idx = tid + i*256;
                int k = idx >> 6, n2 = (idx & 63) * 2;
                __half2 v = *(const __half2*)&Bg[(long)(k0+k)*ldb + n2];
                Bs[n2  ][k] = __low2half(v);
                Bs[n2+1][k] = __high2half(v);
            }
        }
        __syncthreads();
        #pragma unroll
        for (int ks = 0; ks < 2; ks++) {
            int kb = ks * 16;
            uint32_t af[4][4], bf[4][2];
            #pragma unroll
            for (int mt = 0; mt < 4; mt++) {
                int r0 = wm*64 + mt*16 + g;
                af[mt][0] = *(const uint32_t*)&As[r0  ][kb + t4*2    ];
                af[mt][1] = *(const uint32_t*)&As[r0+8][kb + t4*2    ];
                af[mt][2] = *(const uint32_t*)&As[r0  ][kb + t4*2 + 8];
                af[mt][3] = *(const uint32_t*)&As[r0+8][kb + t4*2 + 8];
            }
            #pragma unroll
            for (int nt = 0; nt < 4; nt++) {
                int cc = wn*32 + nt*8 + g;
                bf[nt][0] = *(const uint32_t*)&Bs[cc][kb + t4*2    ];
                bf[nt][1] = *(const uint32_t*)&Bs[cc][kb + t4*2 + 8];
            }
            #pragma unroll
            for (int mt = 0; mt < 4; mt++)
                #pragma unroll
                for (int nt = 0; nt < 4; nt++)
                    MMA16(acc[mt][nt], af[mt], bf[nt]);
        }
        __syncthreads();
    }
    #pragma unroll
    for (int mt = 0; mt < 4; mt++) {
        int row0 = wm*64 + mt*16 + g;
        #pragma unroll
        for (int nt = 0; nt < 4; nt++) {
            int col0 = wn*32 + nt*8 + 2*t4;
            if (OUTMODE == 2) {
                Cg[(long)row0*ldc + col0  ] += acc[mt][nt][0];
                Cg[(long)row0*ldc + col0+1] += acc[mt][nt][1];
                Cg[(long)(row0+8)*ldc + col0  ] += acc[mt][nt][2];
                Cg[(long)(row0+8)*ldc + col0+1] += acc[mt][nt][3];
            } else {
                Cg[(long)row0*ldc + col0  ] = acc[mt][nt][0];
                Cg[(long)row0*ldc + col0+1] = acc[mt][nt][1];
                Cg[(long)(row0+8)*ldc + col0  ] = acc[mt][nt][2];
                Cg[(long)(row0+8)*ldc + col0+1] = acc[mt][nt][3];
            }
        }
    }
}

__global__ __launch_bounds__(256)
void k_ydiag2()
{
    int z = blockIdx.x, bm = blockIdx.y * 128;
    ZIdx zi = zdec(z);
    long brow = (long)zi.b*SEQ + zi.c*CHUNK;
    const __half* Ag = g_LG + (long)z*CHUNK*CHUNK + (long)bm*CHUNK;
    const __half* Bg = g_xdt_h + brow*D_INNER + zi.h*HEADDIM;
    float* Cg = g_y + (brow + bm)*D_INNER + zi.h*HEADDIM;
    int KT = (bm + 128) / 32;
    scan_gemm_core<0,1,0>(Ag, CHUNK, Bg, D_INNER, Cg, D_INNER, KT);
}

__global__ __launch_bounds__(256)
void k_states2()
{
    int z = blockIdx.x;
    ZIdx zi = zdec(z);
    long brow = (long)zi.b*SEQ + zi.c*CHUNK;
    const __half* Ag = g_xdt_h + brow*D_INNER + zi.h*HEADDIM;
    const __half* Bg = g_Bdec + (long)z*CHUNK*D_STATE;
    float* Cg = g_states + (long)z*HEADDIM*D_STATE;
    scan_gemm_core<1,1,1>(Ag, D_INNER, Bg, D_STATE, Cg, D_STATE, CHUNK/32);
}

__global__ __launch_bounds__(256)
void k_yoff2()
{
    int z = blockIdx.x, bm = blockIdx.y * 128;
    ZIdx zi = zdec(z);
    long brow = (long)zi.b*SEQ + zi.c*CHUNK;
    const __half* Ag = g_Cexp + (long)z*CHUNK*D_STATE + (long)bm*D_STATE;
    const __half* Bg = g_sin_h + (long)z*HEADDIM*D_STATE;
    float* Cg = g_y + (brow + bm)*D_INNER + zi.h*HEADDIM;
    scan_gemm_core<0,0,2>(Ag, D_STATE, Bg, D_STATE, Cg, D_INNER, D_STATE/32);
}

// ---------------- prep kernels --------------------------------------------
__global__ __launch_bounds__(256)
void k_prep_lg()
{
    int z = blockIdx.x, lt = blockIdx.y;
    ZIdx zi = zdec(z);
    int bc = z / N_HEADS;
    const float* cum = g_dAcum + ((long)zi.b*N_HEADS + zi.h)*SEQ + zi.c*CHUNK;
    __shared__ float cs[CHUNK];
    if (threadIdx.x < CHUNK) cs[threadIdx.x] = cum[threadIdx.x];
    __syncthreads();
    const __half* G = g_G + (long)bc*CHUNK*CHUNK;
    __half* LG = g_LG + (long)z*CHUNK*CHUNK;
    int tid = threadIdx.x;
    #pragma unroll 4
    for (int j = 0; j < 64; j++) {
        int lin = tid + j*256;
        int l = lt*64 + (lin >> 8);
        int s = lin & 255;
        float v = 0.f;
        if (s <= l) v = __half2float(G[l*CHUNK + s]) * fexp(cs[l] - cs[s]);
        LG[l*CHUNK + s] = __float2half_rn(v);
    }
}

__global__ __launch_bounds__(256)
void k_prep_bc()
{
    int z = blockIdx.x;
    ZIdx zi = zdec(z);
    const float* cum = g_dAcum + ((long)zi.b*N_HEADS + zi.h)*SEQ + zi.c*CHUNK;
    __shared__ float fb[CHUNK], fc[CHUNK];
    if (threadIdx.x < CHUNK) {
        float cl = cum[threadIdx.x];
        fb[threadIdx.x] = fexp(cum[CHUNK-1] - cl);
        fc[threadIdx.x] = fexp(cl);
    }
    __syncthreads();
    long brow = (long)zi.b*SEQ + zi.c*CHUNK;
    __half* Bd = g_Bdec + (long)z*CHUNK*D_STATE;
    __half* Ce = g_Cexp + (long)z*CHUNK*D_STATE;
    int tid = threadIdx.x;
    #pragma unroll 4
    for (int j = 0; j < 128; j++) {
        int lin = tid + j*256;
        int l = lin >> 7, n = lin & 127;
        long bs = brow + l;
        float Bv = __half2float(g_bc_h[bs*(2*D_STATE) + n]);
        float Cv = __half2float(g_bc_h[bs*(2*D_STATE) + D_STATE + n]);
        Bd[lin] = __float2half_rn(Bv * fb[l]);
        Ce[lin] = __float2half_rn(Cv * fc[l]);
    }
}

__global__ __launch_bounds__(256)
void k_tohalf(const float* __restrict__ src, __half* __restrict__ dst, long n2)
{
    long i = (long)blockIdx.x * 256 + threadIdx.x;
    long stride = (long)gridDim.x * 256;
    for (; i < n2; i += stride) {
        float2 v = *reinterpret_cast<const float2*>(src + i*2);
        *reinterpret_cast<__half2*>(dst + i*2) = __floats2half2_rn(v.x, v.y);
    }
}

// ---------------- exact fp32 dt projection + softplus ---------------------
__global__ __launch_bounds__(256)
void k_dtproj(const float* __restrict__ inputs,
              const float* __restrict__ in_proj_w,
              const float* __restrict__ in_proj_b,
              const float* __restrict__ dt_bias)
{
    __shared__ float xs[32][133];
    __shared__ float ws[32][133];
    int t = threadIdx.x;
    long r0 = (long)blockIdx.x * 32;
    int r = t >> 3;
    int hb = (t & 7) * 4;
    const float* Wdt = in_proj_w + (size_t)(D_INNER + CONV_DIM) * DIM;
    float acc[4] = {0.f, 0.f, 0.f, 0.f};
    for (int k0 = 0; k0 < DIM; k0 += 128) {
        #pragma unroll
        for (int i = 0; i < 4; i++) {
            int idx = t + i*256;
            int row = idx >> 5, c4 = (idx & 31) * 4;
            float4 v = *reinterpret_cast<const float4*>(&inputs[(r0+row)*DIM + k0 + c4]);
            xs[row][c4] = v.x; xs[row][c4+1] = v.y; xs[row][c4+2] = v.z; xs[row][c4+3] = v.w;
            float4 w = *reinterpret_cast<const float4*>(&Wdt[(size_t)row*DIM + k0 + c4]);
            ws[row][c4] = w.x; ws[row][c4+1] = w.y; ws[row][c4+2] = w.z; ws[row][c4+3] = w.w;
        }
        __syncthreads();
        #pragma unroll 8
        for (int k = 0; k < 128; k++) {
            float xv = xs[r][k];
            #pragma unroll
            for (int j = 0; j < 4; j++)
                acc[j] = fmaf(xv, ws[hb+j][k], acc[j]);
        }
        __syncthreads();
    }
    #pragma unroll
    for (int j = 0; j < 4; j++) {
        int h = hb + j;
        float x = acc[j] + in_proj_b[D_INNER + CONV_DIM + h] + dt_bias[h];
        g_dt[(r0 + r)*N_HEADS + h] = (x > 20.f) ? x : log1pf(expf(x));
    }
}

// ---------------- tiled conv + SiLU + fused xdt/bc fp16 -------------------
// grid: (CONV_DIM/256, SEQ/32, BATCH), block 256.
// Each block: 256 channels x 32 positions; stages 35 rows in smem.
#define CTS 32
__global__ __launch_bounds__(256)
void k_conv_t(const float* __restrict__ conv_w, const float* __restrict__ conv_b)
{
    __shared__ float xs[CTS + 3][256];
    __shared__ float sdt[CTS][2];        // per-position dt for the 2 heads in block
    int tid = threadIdx.x;
    int c0 = blockIdx.x * 256;
    int s0 = blockIdx.y * CTS;
    int b  = blockIdx.z;
    int c  = c0 + tid;
    long base = ((long)b*SEQ + s0) * D_IN_PROJ + D_INNER + c;

    #pragma unroll
    for (int i = 0; i < CTS + 3; i++) {
        int sp = s0 - 3 + i;
        xs[i][tid] = (sp >= 0) ? g_zxbcdt[base + (long)(i - 3) * D_IN_PROJ] : 0.f;
    }
    bool isx = (c0 < D_INNER);
    if (isx && tid < CTS*2) {
        int j = tid >> 1, hh = tid & 1;
        sdt[j][hh] = g_dt[((long)b*SEQ + s0 + j)*N_HEADS + (c0 >> 7) + hh];
    }
    __syncthreads();

    float w0 = conv_w[c*D_CONV+0], w1 = conv_w[c*D_CONV+1];
    float w2 = conv_w[c*D_CONV+2], w3 = conv_w[c*D_CONV+3];
    float bsv = conv_b[c];
    int hsel = (tid >> 7) & 1;           // which of the block's 2 heads

    #pragma unroll 4
    for (int j = 0; j < CTS; j++) {
        float acc = bsv;
        acc = fmaf(xs[j  ][tid], w0, acc);
        acc = fmaf(xs[j+1][tid], w1, acc);
        acc = fmaf(xs[j+2][tid], w2, acc);
        acc = fmaf(xs[j+3][tid], w3, acc);
        float v = acc / (1.f + expf(-acc));
        long bs = (long)b*SEQ + s0 + j;
        g_xBC[bs*CONV_DIM + c] = v;
        if (isx) {
            g_xdt_h[bs*D_INNER + c] = __float2half_rn(v * sdt[j][hsel]);
        } else {
            int cc = c - D_INNER;
            if (cc >= 0)
                g_bc_h[bs*(2*D_STATE) + cc] = __float2half_rn(v);
        }
    }
}

// ---------------- chunk-local inclusive cumsum of A*dt --------------------
__global__ __launch_bounds__(CHUNK)
void k_cumsum(const float* __restrict__ A_log)
{
    int bz = blockIdx.x;
    int c = bz % NCHUNK; int bh = bz / NCHUNK;
    int h = bh % N_HEADS; int b = bh / N_HEADS;
    int l = threadIdx.x;
    int sg = c*CHUNK + l;
    float A = -expf(A_log[h]);
    float val = A * g_dt[((long)b*SEQ + sg)*N_HEADS + h];
    __shared__ float buf[CHUNK];
    buf[l] = val; __syncthreads();
    for (int off = 1; off < CHUNK; off <<= 1) {
        float t = (l >= off) ? buf[l-off] : 0.f;
        __syncthreads();
        buf[l] += t;
        __syncthreads();
    }
    g_dAcum[((long)b*N_HEADS + h)*SEQ + sg] = buf[l];
}

// ---------------- inter-chunk recurrence (-> Sin fp16), full-chip ---------
__global__ __launch_bounds__(256)
void k_chunkrec()
{
    int bh = blockIdx.x;
    int h = bh % N_HEADS; int b = bh / N_HEADS;
    const float* cum = g_dAcum + (long)bh*SEQ;
    float csum[NCHUNK];
    #pragma unroll
    for (int c = 0; c < NCHUNK; c++) csum[c] = expf(cum[c*CHUNK + CHUNK-1]);
    int pn0 = blockIdx.y * (HEADDIM*D_STATE/8);
    #pragma unroll
    for (int j = 0; j < (HEADDIM*D_STATE/8)/256; j++) {
        int pn = pn0 + j*256 + threadIdx.x;
        float carry = 0.f;
        #pragma unroll
        for (int c = 0; c < NCHUNK; c++) {
            long z = ((long)b*NCHUNK + c)*N_HEADS + h;
            long idx = z*HEADDIM*D_STATE + pn;
            g_sin_h[idx] = __float2half_rn(carry);
            carry = carry * csum[c] + g_states[idx];
        }
    }
}

// ---------------- gate (y + D*x) * silu(z) + RMSNorm -> fp16 --------------
__global__ __launch_bounds__(256)
void k_gatenorm(const float* __restrict__ norm_w, const float* __restrict__ Dv)
{
    long row = blockIdx.x;
    const float* zrow = g_zxbcdt + row*D_IN_PROJ;
    const float* xrow = g_xBC + row*CONV_DIM;
    float* yrow = g_y + row*D_INNER;
    __half* yh = g_y_h + row*D_INNER;
    float vals[16];
    float local = 0.f;
    #pragma unroll
    for (int i = 0; i < 16; i++) {
        int d = threadIdx.x + i*256;
        float z = zrow[d];
        float v = (yrow[d] + Dv[d >> 7] * xrow[d]) * (z / (1.f + expf(-z)));
        vals[i] = v;
        local += v * v;
    }
    __shared__ float red[256];
    red[threadIdx.x] = local; __syncthreads();
    for (int off = 128; off > 0; off >>= 1) {
        if (threadIdx.x < off) red[threadIdx.x] += red[threadIdx.x + off];
        __syncthreads();
    }
    float scale = rsqrtf(red[0] / D_INNER + EPS);
    #pragma unroll
    for (int i = 0; i < 16; i++) {
        int d = threadIdx.x + i*256;
        yh[d] = __float2half_rn(vals[i] * scale * norm_w[d]);
    }
}

// --------------------------------------------------------------------------
extern "C" void kernel_launch(void* const* d_in, const int* in_sizes, int n_in,
                              void* d_out, int out_size)
{
    const float* inputs     = (const float*)d_in[0];
    const float* in_proj_w  = (const float*)d_in[1];
    const float* in_proj_b  = (const float*)d_in[2];
    const float* out_proj_w = (const float*)d_in[3];
    const float* out_proj_b = (const float*)d_in[4];
    const float* conv_w     = (const float*)d_in[5];
    const float* conv_b     = (const float*)d_in[6];
    const float* dt_bias    = (const float*)d_in[7];
    const float* A_log      = (const float*)d_in[8];
    const float* Dv         = (const float*)d_in[9];
    const float* norm_w     = (const float*)d_in[10];
    float* out = (float*)d_out;

    float *zx;
    __half *Gp, *inh, *winh, *wouth, *yh, *bch;
    cudaGetSymbolAddress((void**)&zx,    g_zxbcdt);
    cudaGetSymbolAddress((void**)&Gp,    g_G);
    cudaGetSymbolAddress((void**)&inh,   g_in_h);
    cudaGetSymbolAddress((void**)&winh,  g_win_h);
    cudaGetSymbolAddress((void**)&wouth, g_wout_h);
    cudaGetSymbolAddress((void**)&yh,    g_y_h);
    cudaGetSymbolAddress((void**)&bch,   g_bc_h);

    cudaFuncSetAttribute(gemm_h<float>, cudaFuncAttributeMaxDynamicSharedMemorySize, GSMEM);
    cudaFuncSetAttribute(gemm_h<__half>, cudaFuncAttributeMaxDynamicSharedMemorySize, GSMEM);

    const int M = BATCH * SEQ;     // 4096

    // 0) fp16 mirrors
    k_tohalf<<<2048, 256>>>(inputs,     inh,   (long)M*DIM/2);
    k_tohalf<<<2048, 256>>>(in_proj_w,  winh,  (long)D_IN_PROJ*DIM/2);
    k_tohalf<<<2048, 256>>>(out_proj_w, wouth, (long)DIM*D_INNER/2);

    // 1) in_proj
    {
        dim3 grid((D_IN_PROJ + 127)/128, M/128, 1);
        gemm_h<float><<<grid, 256, GSMEM>>>(inh, DIM, 0, winh, DIM, 0,
                              zx, D_IN_PROJ, 0, M, D_IN_PROJ, DIM, in_proj_b);
    }
    // 2) exact dt projection (before conv: conv consumes dt)
    k_dtproj<<<M/32, 256>>>(inputs, in_proj_w, in_proj_b, dt_bias);
    // 3) tiled conv + silu, fused xdt/bc fp16 production
    {
        dim3 grid(CONV_DIM/256, SEQ/CTS, BATCH);
        k_conv_t<<<grid, 256>>>(conv_w, conv_b);
    }
    // 4) cumsum
    k_cumsum<<<BATCH*N_HEADS*NCHUNK, CHUNK>>>(A_log);
    // 5) G = C @ B^T per (b,c), fp16 output
    {
        dim3 grid(CHUNK/128, CHUNK/128, BATCH*NCHUNK);
        gemm_h<__half><<<grid, 256, GSMEM>>>(bch + D_STATE, 2*D_STATE, (long)CHUNK*2*D_STATE,
                              bch,           2*D_STATE, (long)CHUNK*2*D_STATE,
                              Gp, CHUNK, (long)CHUNK*CHUNK,
                              CHUNK, CHUNK, D_STATE, nullptr);
    }
    // 6) preps
    {
        dim3 grid(NBCH, CHUNK/64);
        k_prep_lg<<<grid, 256>>>();
    }
    k_prep_bc<<<NBCH, 256>>>();
    // 7) Y_diag (tensor)
    {
        dim3 grid(NBCH, CHUNK/128);
        k_ydiag2<<<grid, 256>>>();
    }
    // 8) states (tensor)
    k_states2<<<NBCH, 256>>>();
    // 9) inter-chunk recurrence -> Sin fp16 (full-chip)
    {
        dim3 grid(BATCH*N_HEADS, 8);
        k_chunkrec<<<grid, 256>>>();
    }
    // 10) Y_off += (tensor)
    {
        dim3 grid(NBCH, CHUNK/128);
        k_yoff2<<<grid, 256>>>();
    }
    // 11) gate + D*x + RMSNorm -> fp16
    k_gatenorm<<<BATCH*SEQ, 256>>>(norm_w, Dv);
    // 12) out_proj
    {
        dim3 grid(DIM/128, M/128, 1);
        gemm_h<float><<<grid, 256, GSMEM>>>(yh, D_INNER, 0, wouth, D_INNER, 0,
                              out, DIM, 0, M, DIM, D_INNER, out_proj_b);
    }
}

// round 15
// speedup vs baseline: 1.4474x; 1.4474x over previous
#include <cuda_runtime.h>
#include <cuda_fp16.h>
#include <math.h>
#include <stdint.h>

#define BATCH   2
#define SEQ     2048
#define DIM     2048
#define D_INNER 4096
#define D_STATE 128
#define N_HEADS 32
#define HEADDIM 128
#define D_CONV  4
#define CHUNK   256
#define NCHUNK  (SEQ/CHUNK)                       /* 8  */
#define NBCH    (BATCH*NCHUNK*N_HEADS)            /* 512 */
#define CONV_DIM (D_INNER + 2*D_STATE)            /* 4352 */
#define D_IN_PROJ (2*D_INNER + 2*D_STATE + N_HEADS) /* 8480 */
#define EPS 1e-5f

// ---------------- scratch (device globals, no allocation) ----------------
__device__ float g_zxbcdt[(size_t)BATCH*SEQ*D_IN_PROJ];
__device__ float g_xBC  [(size_t)BATCH*SEQ*CONV_DIM];
__device__ float g_dt   [(size_t)BATCH*SEQ*N_HEADS];
__device__ float g_dAcum[(size_t)BATCH*N_HEADS*SEQ];
__device__ float g_G    [(size_t)BATCH*NCHUNK*CHUNK*CHUNK];
__device__ float g_states[(size_t)NBCH*HEADDIM*D_STATE];
__device__ float g_y    [(size_t)BATCH*SEQ*D_INNER];
// fp16 operand mirrors
__device__ __half g_in_h  [(size_t)BATCH*SEQ*DIM];
__device__ __half g_win_h [(size_t)D_IN_PROJ*DIM];
__device__ __half g_wout_h[(size_t)DIM*D_INNER];
__device__ __half g_y_h   [(size_t)BATCH*SEQ*D_INNER];
__device__ __half g_bc_h  [(size_t)BATCH*SEQ*2*D_STATE];
// fp16 scan operands
__device__ __half g_xdt_h [(size_t)BATCH*SEQ*D_INNER];
__device__ __half g_LG    [(size_t)NBCH*CHUNK*CHUNK];
__device__ __half g_Bdec  [(size_t)NBCH*CHUNK*D_STATE];
__device__ __half g_Cexp  [(size_t)NBCH*CHUNK*D_STATE];
__device__ __half g_sin_h [(size_t)NBCH*HEADDIM*D_STATE];

__device__ __forceinline__ void cp16(uint32_t dst, const void* src, bool pred) {
    asm volatile("cp.async.cg.shared.global [%0], [%1], 16, %2;"
                 :: "r"(dst), "l"(src), "r"(pred ? 16 : 0));
}
__device__ __forceinline__ void ldsm4(uint32_t* r, uint32_t addr) {
    asm volatile("ldmatrix.sync.aligned.m8n8.x4.shared.b16 {%0,%1,%2,%3}, [%4];"
        : "=r"(r[0]), "=r"(r[1]), "=r"(r[2]), "=r"(r[3]) : "r"(addr));
}
// fast exp on FMA pipe: exp(x) for x<=0
__device__ __forceinline__ float fexp(float x) {
    float t = x * 1.4426950408889634f;
    t = fmaxf(t, -25.f);
    float fi = floorf(t);
    float f = t - fi;
    float p = 1.f + f*(0.69314718f + f*(0.24022651f + f*(0.05550411f
            + f*(0.00961813f + f*0.00133336f))));
    return p * __int_as_float(((int)fi + 127) << 23);
}

#define MMA16(acc, af, bf)                                                   \
    asm volatile(                                                            \
        "mma.sync.aligned.m16n8k16.row.col.f32.f16.f16.f32 "                 \
        "{%0,%1,%2,%3}, {%4,%5,%6,%7}, {%8,%9}, {%0,%1,%2,%3};"              \
        : "+f"(acc[0]), "+f"(acc[1]), "+f"(acc[2]), "+f"(acc[3])             \
        : "r"(af[0]), "r"(af[1]), "r"(af[2]), "r"(af[3]),                    \
          "r"(bf[0]), "r"(bf[1]))

// ================== fp16 mma.sync batched NT GEMM (projections) ===========
// BK=64, 3-stage cp.async, XOR-swizzled smem (no pad), ldmatrix fragments.
// (verbatim from Round-13 winning version)
#define GSTG (128*64*2)               /* 16384 B per operand-stage */
#define GSMEM (6*GSTG)                /* 98304 */
__global__ __launch_bounds__(256, 2)
void gemm_h(const __half* __restrict__ A, long lda, long sA,
            const __half* __restrict__ W, long ldb, long sB,
            float* __restrict__ C, long ldc, long sC,
            int M, int N, int K, const float* __restrict__ bias)
{
    extern __shared__ char smem[];
    int bz = blockIdx.z;
    const __half* Ab = A + (long)bz * sA;
    const __half* Wb = W + (long)bz * sB;
    float*        Cb = C + (long)bz * sC;
    int bm = blockIdx.y * 128, bn = blockIdx.x * 128;
    int tid  = threadIdx.x;
    int warp = tid >> 5, lane = tid & 31;
    int wm = warp >> 2, wn = warp & 3;
    int g  = lane >> 2, t4 = lane & 3;

    uint32_t sAu = (uint32_t)__cvta_generic_to_shared(smem);
    uint32_t sBu = sAu + 3*GSTG;

    int arow = lane & 15;
    int achk = lane >> 4;
    int brow = ((lane >> 4) << 3) + (lane & 7);
    int bchk = (lane >> 3) & 1;

    float acc[4][4][4];
    #pragma unroll
    for (int i = 0; i < 4; i++)
        #pragma unroll
        for (int j = 0; j < 4; j++)
            #pragma unroll
            for (int q = 0; q < 4; q++) acc[i][j][q] = 0.f;

    const int KT = K / 64;

    #define LOADTILE(st, k0)                                                  \
    do {                                                                      \
        _Pragma("unroll")                                                     \
        for (int it = 0; it < 4; it++) {                                      \
            int idx = tid + it*256;                                           \
            int row = idx >> 3, c8 = idx & 7;                                 \
            int sc = c8 ^ (row & 7);                                          \
            cp16(sAu + (st)*GSTG + row*128 + sc*16,                           \
                 &Ab[(long)(bm+row)*lda + (k0) + c8*8], true);                \
        }                                                                     \
        _Pragma("unroll")                                                     \
        for (int it = 0; it < 4; it++) {                                      \
            int idx = tid + it*256;                                           \
            int row = idx >> 3, c8 = idx & 7;                                 \
            int sc = c8 ^ (row & 7);                                          \
            int gn = bn + row; bool p = gn < N;                               \
            cp16(sBu + (st)*GSTG + row*128 + sc*16,                           \
                 &Wb[(long)(p ? gn : 0)*ldb + (k0) + c8*8], p);               \
        }                                                                     \
    } while (0)

    LOADTILE(0, 0);
    asm volatile("cp.async.commit_group;");
    if (KT > 1) LOADTILE(1, 64);
    asm volatile("cp.async.commit_group;");

    for (int kt = 0; kt < KT; kt++) {
        asm volatile("cp.async.wait_group 1;" ::: "memory");
        __syncthreads();
        if (kt + 2 < KT) LOADTILE((kt+2) % 3, (kt+2)*64);
        asm volatile("cp.async.commit_group;");

        int st = kt % 3;
        #pragma unroll
        for (int ks = 0; ks < 4; ks++) {
            uint32_t af[4][4], bf[4][2];
            #pragma unroll
            for (int mt = 0; mt < 4; mt++) {
                int r = wm*64 + mt*16 + arow;
                int chk = (ks*2 + achk) ^ (r & 7);
                ldsm4(af[mt], sAu + st*GSTG + r*128 + chk*16);
            }
            #pragma unroll
            for (int np = 0; np < 2; np++) {
                int r = wn*32 + np*16 + brow;
                int chk = (ks*2 + bchk) ^ (r & 7);
                uint32_t t[4];
                ldsm4(t, sBu + st*GSTG + r*128 + chk*16);
                bf[np*2  ][0] = t[0]; bf[np*2  ][1] = t[1];
                bf[np*2+1][0] = t[2]; bf[np*2+1][1] = t[3];
            }
            #pragma unroll
            for (int mt = 0; mt < 4; mt++)
                #pragma unroll
                for (int nt = 0; nt < 4; nt++)
                    MMA16(acc[mt][nt], af[mt], bf[nt]);
        }
        __syncthreads();
    }
    #undef LOADTILE

    #pragma unroll
    for (int mt = 0; mt < 4; mt++) {
        int row0 = bm + wm*64 + mt*16 + g;
        #pragma unroll
        for (int nt = 0; nt < 4; nt++) {
            int col0 = bn + wn*32 + nt*8 + 2*t4;
            if (col0 < N) {
                float b0 = bias ? bias[col0] : 0.f;
                Cb[(long)row0*ldc + col0] = acc[mt][nt][0] + b0;
                Cb[(long)(row0+8)*ldc + col0] = acc[mt][nt][2] + b0;
            }
            if (col0+1 < N) {
                float b1 = bias ? bias[col0+1] : 0.f;
                Cb[(long)row0*ldc + col0+1] = acc[mt][nt][1] + b1;
                Cb[(long)(row0+8)*ldc + col0+1] = acc[mt][nt][3] + b1;
            }
        }
    }
}

// =============== scan GEMMs: 128x128 tile, K-step 32, fp16 ================
#define SS 42

struct ZIdx { int b, c, h; };
__device__ __forceinline__ ZIdx zdec(int z) {
    ZIdx r; r.h = z % N_HEADS; int bc = z / N_HEADS;
    r.c = bc % NCHUNK; r.b = bc / NCHUNK; return r;
}

template<int STAGEA, int STAGEB, int OUTMODE>
__device__ __forceinline__ void scan_gemm_core(
    const __half* Ag, long lda,
    const __half* Bg, long ldb,
    float* Cg, long ldc,
    int KT)
{
    __shared__ __half As[128][SS];
    __shared__ __half Bs[128][SS];
    int tid = threadIdx.x;
    int warp = tid >> 5, lane = tid & 31;
    int wm = warp >> 2, wn = warp & 3;
    int g = lane >> 2, t4 = lane & 3;

    float acc[4][4][4];
    #pragma unroll
    for (int i = 0; i < 4; i++)
        #pragma unroll
        for (int j = 0; j < 4; j++)
            #pragma unroll
            for (int q = 0; q < 4; q++) acc[i][j][q] = 0.f;

    for (int kt = 0; kt < KT; kt++) {
        int k0 = kt * 32;
        if (STAGEA == 0) {
            #pragma unroll
            for (int i = 0; i < 8; i++) {
                int idx = tid + i*256;
                int row = idx >> 4, c2 = (idx & 15) * 2;
                *(__half2*)&As[row][c2] = *(const __half2*)&Ag[(long)row*lda + k0 + c2];
            }
        } else {
            #pragma unroll
            for (int i = 0; i < 8; i++) {
                int idx = tid + i*256;
                int k = idx >> 6, m2 = (idx & 63) * 2;
                __half2 v = *(const __half2*)&Ag[(long)(k0+k)*lda + m2];
                As[m2  ][k] = __low2half(v);
                As[m2+1][k] = __high2half(v);
            }
        }
        if (STAGEB == 0) {
            #pragma unroll
            for (int i = 0; i < 8; i++) {
                int idx = tid + i*256;
                int row = idx >> 4, c2 = (idx & 15) * 2;
                *(__half2*)&Bs[row][c2] = *(const __half2*)&Bg[(long)row*ldb + k0 + c2];
            }
        } else {
            #pragma unroll
            for (int i = 0; i < 8; i++) {
                int idx = tid + i*256;
                int k = idx >> 6, n2 = (idx & 63) * 2;
                __half2 v = *(const __half2*)&Bg[(long)(k0+k)*ldb + n2];
                Bs[n2  ][k] = __low2half(v);
                Bs[n2+1][k] = __high2half(v);
            }
        }
        __syncthreads();
        #pragma unroll
        for (int ks = 0; ks < 2; ks++) {
            int kb = ks * 16;
            uint32_t af[4][4], bf[4][2];
            #pragma unroll
            for (int mt = 0; mt < 4; mt++) {
                int r0 = wm*64 + mt*16 + g;
                af[mt][0] = *(const uint32_t*)&As[r0  ][kb + t4*2    ];
                af[mt][1] = *(const uint32_t*)&As[r0+8][kb + t4*2    ];
                af[mt][2] = *(const uint32_t*)&As[r0  ][kb + t4*2 + 8];
                af[mt][3] = *(const uint32_t*)&As[r0+8][kb + t4*2 + 8];
            }
            #pragma unroll
            for (int nt = 0; nt < 4; nt++) {
                int cc = wn*32 + nt*8 + g;
                bf[nt][0] = *(const uint32_t*)&Bs[cc][kb + t4*2    ];
                bf[nt][1] = *(const uint32_t*)&Bs[cc][kb + t4*2 + 8];
            }
            #pragma unroll
            for (int mt = 0; mt < 4; mt++)
                #pragma unroll
                for (int nt = 0; nt < 4; nt++)
                    MMA16(acc[mt][nt], af[mt], bf[nt]);
        }
        __syncthreads();
    }
    #pragma unroll
    for (int mt = 0; mt < 4; mt++) {
        int row0 = wm*64 + mt*16 + g;
        #pragma unroll
        for (int nt = 0; nt < 4; nt++) {
            int col0 = wn*32 + nt*8 + 2*t4;
            if (OUTMODE == 2) {
                Cg[(long)row0*ldc + col0  ] += acc[mt][nt][0];
                Cg[(long)row0*ldc + col0+1] += acc[mt][nt][1];
                Cg[(long)(row0+8)*ldc + col0  ] += acc[mt][nt][2];
                Cg[(long)(row0+8)*ldc + col0+1] += acc[mt][nt][3];
            } else {
                Cg[(long)row0*ldc + col0  ] = acc[mt][nt][0];
                Cg[(long)row0*ldc + col0+1] = acc[mt][nt][1];
                Cg[(long)(row0+8)*ldc + col0  ] = acc[mt][nt][2];
                Cg[(long)(row0+8)*ldc + col0+1] = acc[mt][nt][3];
            }
        }
    }
}

__global__ __launch_bounds__(256)
void k_ydiag2()
{
    int z = blockIdx.x, bm = blockIdx.y * 128;
    ZIdx zi = zdec(z);
    long brow = (long)zi.b*SEQ + zi.c*CHUNK;
    const __half* Ag = g_LG + (long)z*CHUNK*CHUNK + (long)bm*CHUNK;
    const __half* Bg = g_xdt_h + brow*D_INNER + zi.h*HEADDIM;
    float* Cg = g_y + (brow + bm)*D_INNER + zi.h*HEADDIM;
    int KT = (bm + 128) / 32;
    scan_gemm_core<0,1,0>(Ag, CHUNK, Bg, D_INNER, Cg, D_INNER, KT);
}

__global__ __launch_bounds__(256)
void k_states2()
{
    int z = blockIdx.x;
    ZIdx zi = zdec(z);
    long brow = (long)zi.b*SEQ + zi.c*CHUNK;
    const __half* Ag = g_xdt_h + brow*D_INNER + zi.h*HEADDIM;
    const __half* Bg = g_Bdec + (long)z*CHUNK*D_STATE;
    float* Cg = g_states + (long)z*HEADDIM*D_STATE;
    scan_gemm_core<1,1,1>(Ag, D_INNER, Bg, D_STATE, Cg, D_STATE, CHUNK/32);
}

__global__ __launch_bounds__(256)
void k_yoff2()
{
    int z = blockIdx.x, bm = blockIdx.y * 128;
    ZIdx zi = zdec(z);
    long brow = (long)zi.b*SEQ + zi.c*CHUNK;
    const __half* Ag = g_Cexp + (long)z*CHUNK*D_STATE + (long)bm*D_STATE;
    const __half* Bg = g_sin_h + (long)z*HEADDIM*D_STATE;
    float* Cg = g_y + (brow + bm)*D_INNER + zi.h*HEADDIM;
    scan_gemm_core<0,0,2>(Ag, D_STATE, Bg, D_STATE, Cg, D_INNER, D_STATE/32);
}

// ---------------- prep kernels --------------------------------------------
__global__ __launch_bounds__(256)
void k_prep_lg()
{
    int z = blockIdx.x, lt = blockIdx.y;
    ZIdx zi = zdec(z);
    int bc = z / N_HEADS;
    const float* cum = g_dAcum + ((long)zi.b*N_HEADS + zi.h)*SEQ + zi.c*CHUNK;
    __shared__ float cs[CHUNK];
    if (threadIdx.x < CHUNK) cs[threadIdx.x] = cum[threadIdx.x];
    __syncthreads();
    const float* G = g_G + (long)bc*CHUNK*CHUNK;
    __half* LG = g_LG + (long)z*CHUNK*CHUNK;
    int tid = threadIdx.x;
    #pragma unroll 4
    for (int j = 0; j < 64; j++) {
        int lin = tid + j*256;
        int l = lt*64 + (lin >> 8);
        int s = lin & 255;
        float v = 0.f;
        if (s <= l) v = G[l*CHUNK + s] * fexp(cs[l] - cs[s]);
        LG[l*CHUNK + s] = __float2half_rn(v);
    }
}

__global__ __launch_bounds__(256)
void k_prep_bc()
{
    int z = blockIdx.x;
    ZIdx zi = zdec(z);
    const float* cum = g_dAcum + ((long)zi.b*N_HEADS + zi.h)*SEQ + zi.c*CHUNK;
    __shared__ float fb[CHUNK], fc[CHUNK];
    if (threadIdx.x < CHUNK) {
        float cl = cum[threadIdx.x];
        fb[threadIdx.x] = fexp(cum[CHUNK-1] - cl);
        fc[threadIdx.x] = fexp(cl);
    }
    __syncthreads();
    long brow = (long)zi.b*SEQ + zi.c*CHUNK;
    __half* Bd = g_Bdec + (long)z*CHUNK*D_STATE;
    __half* Ce = g_Cexp + (long)z*CHUNK*D_STATE;
    int tid = threadIdx.x;
    #pragma unroll 4
    for (int j = 0; j < 128; j++) {
        int lin = tid + j*256;
        int l = lin >> 7, n = lin & 127;
        long bs = brow + l;
        float Bv = __half2float(g_bc_h[bs*(2*D_STATE) + n]);
        float Cv = __half2float(g_bc_h[bs*(2*D_STATE) + D_STATE + n]);
        Bd[lin] = __float2half_rn(Bv * fb[l]);
        Ce[lin] = __float2half_rn(Cv * fc[l]);
    }
}

__global__ __launch_bounds__(256)
void k_tohalf(const float* __restrict__ src, __half* __restrict__ dst, long n2)
{
    long i = (long)blockIdx.x * 256 + threadIdx.x;
    long stride = (long)gridDim.x * 256;
    for (; i < n2; i += stride) {
        float2 v = *reinterpret_cast<const float2*>(src + i*2);
        *reinterpret_cast<__half2*>(dst + i*2) = __floats2half2_rn(v.x, v.y);
    }
}

// ---------------- exact fp32 dt projection + softplus ---------------------
__global__ __launch_bounds__(256)
void k_dtproj(const float* __restrict__ inputs,
              const float* __restrict__ in_proj_w,
              const float* __restrict__ in_proj_b,
              const float* __restrict__ dt_bias)
{
    __shared__ float xs[32][133];
    __shared__ float ws[32][133];
    int t = threadIdx.x;
    long r0 = (long)blockIdx.x * 32;
    int r = t >> 3;
    int hb = (t & 7) * 4;
    const float* Wdt = in_proj_w + (size_t)(D_INNER + CONV_DIM) * DIM;
    float acc[4] = {0.f, 0.f, 0.f, 0.f};
    for (int k0 = 0; k0 < DIM; k0 += 128) {
        #pragma unroll
        for (int i = 0; i < 4; i++) {
            int idx = t + i*256;
            int row = idx >> 5, c4 = (idx & 31) * 4;
            float4 v = *reinterpret_cast<const float4*>(&inputs[(r0+row)*DIM + k0 + c4]);
            xs[row][c4] = v.x; xs[row][c4+1] = v.y; xs[row][c4+2] = v.z; xs[row][c4+3] = v.w;
            float4 w = *reinterpret_cast<const float4*>(&Wdt[(size_t)row*DIM + k0 + c4]);
            ws[row][c4] = w.x; ws[row][c4+1] = w.y; ws[row][c4+2] = w.z; ws[row][c4+3] = w.w;
        }
        __syncthreads();
        #pragma unroll 8
        for (int k = 0; k < 128; k++) {
            float xv = xs[r][k];
            #pragma unroll
            for (int j = 0; j < 4; j++)
                acc[j] = fmaf(xv, ws[hb+j][k], acc[j]);
        }
        __syncthreads();
    }
    #pragma unroll
    for (int j = 0; j < 4; j++) {
        int h = hb + j;
        float x = acc[j] + in_proj_b[D_INNER + CONV_DIM + h] + dt_bias[h];
        g_dt[(r0 + r)*N_HEADS + h] = (x > 20.f) ? x : log1pf(expf(x));
    }
}

// ---------------- tiled conv + SiLU + fused xdt/bc fp16 -------------------
// grid: (CONV_DIM/256, SEQ/32, BATCH), block 256; 35 rows staged in smem.
#define CTS 32
__global__ __launch_bounds__(256)
void k_conv_t(const float* __restrict__ conv_w, const float* __restrict__ conv_b)
{
    __shared__ float xs[CTS + 3][256];
    __shared__ float sdt[CTS][2];
    int tid = threadIdx.x;
    int c0 = blockIdx.x * 256;
    int s0 = blockIdx.y * CTS;
    int b  = blockIdx.z;
    int c  = c0 + tid;
    long base = ((long)b*SEQ + s0) * D_IN_PROJ + D_INNER + c;

    #pragma unroll
    for (int i = 0; i < CTS + 3; i++) {
        int sp = s0 - 3 + i;
        xs[i][tid] = (sp >= 0) ? g_zxbcdt[base + (long)(i - 3) * D_IN_PROJ] : 0.f;
    }
    bool isx = (c0 < D_INNER);
    if (isx && tid < CTS*2) {
        int j = tid >> 1, hh = tid & 1;
        sdt[j][hh] = g_dt[((long)b*SEQ + s0 + j)*N_HEADS + (c0 >> 7) + hh];
    }
    __syncthreads();

    float w0 = conv_w[c*D_CONV+0], w1 = conv_w[c*D_CONV+1];
    float w2 = conv_w[c*D_CONV+2], w3 = conv_w[c*D_CONV+3];
    float bsv = conv_b[c];
    int hsel = (tid >> 7) & 1;

    #pragma unroll 4
    for (int j = 0; j < CTS; j++) {
        float acc = bsv;
        acc = fmaf(xs[j  ][tid], w0, acc);
        acc = fmaf(xs[j+1][tid], w1, acc);
        acc = fmaf(xs[j+2][tid], w2, acc);
        acc = fmaf(xs[j+3][tid], w3, acc);
        float v = acc / (1.f + expf(-acc));
        long bs = (long)b*SEQ + s0 + j;
        g_xBC[bs*CONV_DIM + c] = v;
        if (isx) {
            g_xdt_h[bs*D_INNER + c] = __float2half_rn(v * sdt[j][hsel]);
        } else {
            int cc = c - D_INNER;
            if (cc >= 0)
                g_bc_h[bs*(2*D_STATE) + cc] = __float2half_rn(v);
        }
    }
}

// ---------------- chunk-local inclusive cumsum of A*dt --------------------
__global__ __launch_bounds__(CHUNK)
void k_cumsum(const float* __restrict__ A_log)
{
    int bz = blockIdx.x;
    int c = bz % NCHUNK; int bh = bz / NCHUNK;
    int h = bh % N_HEADS; int b = bh / N_HEADS;
    int l = threadIdx.x;
    int sg = c*CHUNK + l;
    float A = -expf(A_log[h]);
    float val = A * g_dt[((long)b*SEQ + sg)*N_HEADS + h];
    __shared__ float buf[CHUNK];
    buf[l] = val; __syncthreads();
    for (int off = 1; off < CHUNK; off <<= 1) {
        float t = (l >= off) ? buf[l-off] : 0.f;
        __syncthreads();
        buf[l] += t;
        __syncthreads();
    }
    g_dAcum[((long)b*N_HEADS + h)*SEQ + sg] = buf[l];
}

// ---------------- inter-chunk recurrence (-> Sin fp16), full-chip ---------
__global__ __launch_bounds__(256)
void k_chunkrec()
{
    int bh = blockIdx.x;
    int h = bh % N_HEADS; int b = bh / N_HEADS;
    const float* cum = g_dAcum + (long)bh*SEQ;
    float csum[NCHUNK];
    #pragma unroll
    for (int c = 0; c < NCHUNK; c++) csum[c] = expf(cum[c*CHUNK + CHUNK-1]);
    int pn0 = blockIdx.y * (HEADDIM*D_STATE/8);
    #pragma unroll
    for (int j = 0; j < (HEADDIM*D_STATE/8)/256; j++) {
        int pn = pn0 + j*256 + threadIdx.x;
        float carry = 0.f;
        #pragma unroll
        for (int c = 0; c < NCHUNK; c++) {
            long z = ((long)b*NCHUNK + c)*N_HEADS + h;
            long idx = z*HEADDIM*D_STATE + pn;
            g_sin_h[idx] = __float2half_rn(carry);
            carry = carry * csum[c] + g_states[idx];
        }
    }
}

// ---------------- gate (y + D*x) * silu(z) + RMSNorm -> fp16 --------------
__global__ __launch_bounds__(256)
void k_gatenorm(const float* __restrict__ norm_w, const float* __restrict__ Dv)
{
    long row = blockIdx.x;
    const float* zrow = g_zxbcdt + row*D_IN_PROJ;
    const float* xrow = g_xBC + row*CONV_DIM;
    float* yrow = g_y + row*D_INNER;
    __half* yh = g_y_h + row*D_INNER;
    float vals[16];
    float local = 0.f;
    #pragma unroll
    for (int i = 0; i < 16; i++) {
        int d = threadIdx.x + i*256;
        float z = zrow[d];
        float v = (yrow[d] + Dv[d >> 7] * xrow[d]) * (z / (1.f + expf(-z)));
        vals[i] = v;
        local += v * v;
    }
    __shared__ float red[256];
    red[threadIdx.x] = local; __syncthreads();
    for (int off = 128; off > 0; off >>= 1) {
        if (threadIdx.x < off) red[threadIdx.x] += red[threadIdx.x + off];
        __syncthreads();
    }
    float scale = rsqrtf(red[0] / D_INNER + EPS);
    #pragma unroll
    for (int i = 0; i < 16; i++) {
        int d = threadIdx.x + i*256;
        yh[d] = __float2half_rn(vals[i] * scale * norm_w[d]);
    }
}

// --------------------------------------------------------------------------
extern "C" void kernel_launch(void* const* d_in, const int* in_sizes, int n_in,
                              void* d_out, int out_size)
{
    const float* inputs     = (const float*)d_in[0];
    const float* in_proj_w  = (const float*)d_in[1];
    const float* in_proj_b  = (const float*)d_in[2];
    const float* out_proj_w = (const float*)d_in[3];
    const float* out_proj_b = (const float*)d_in[4];
    const float* conv_w     = (const float*)d_in[5];
    const float* conv_b     = (const float*)d_in[6];
    const float* dt_bias    = (const float*)d_in[7];
    const float* A_log      = (const float*)d_in[8];
    const float* Dv         = (const float*)d_in[9];
    const float* norm_w     = (const float*)d_in[10];
    float* out = (float*)d_out;

    float *zx, *Gp;
    __half *inh, *winh, *wouth, *yh, *bch;
    cudaGetSymbolAddress((void**)&zx,    g_zxbcdt);
    cudaGetSymbolAddress((void**)&Gp,    g_G);
    cudaGetSymbolAddress((void**)&inh,   g_in_h);
    cudaGetSymbolAddress((void**)&winh,  g_win_h);
    cudaGetSymbolAddress((void**)&wouth, g_wout_h);
    cudaGetSymbolAddress((void**)&yh,    g_y_h);
    cudaGetSymbolAddress((void**)&bch,   g_bc_h);

    cudaFuncSetAttribute(gemm_h, cudaFuncAttributeMaxDynamicSharedMemorySize, GSMEM);

    const int M = BATCH * SEQ;     // 4096

    // 0) fp16 mirrors
    k_tohalf<<<2048, 256>>>(inputs,     inh,   (long)M*DIM/2);
    k_tohalf<<<2048, 256>>>(in_proj_w,  winh,  (long)D_IN_PROJ*DIM/2);
    k_tohalf<<<2048, 256>>>(out_proj_w, wouth, (long)DIM*D_INNER/2);

    // 1) in_proj
    {
        dim3 grid((D_IN_PROJ + 127)/128, M/128, 1);
        gemm_h<<<grid, 256, GSMEM>>>(inh, DIM, 0, winh, DIM, 0,
                              zx, D_IN_PROJ, 0, M, D_IN_PROJ, DIM, in_proj_b);
    }
    // 2) exact dt projection (before conv: conv consumes dt)
    k_dtproj<<<M/32, 256>>>(inputs, in_proj_w, in_proj_b, dt_bias);
    // 3) tiled conv + silu, fused xdt/bc fp16 production
    {
        dim3 grid(CONV_DIM/256, SEQ/CTS, BATCH);
        k_conv_t<<<grid, 256>>>(conv_w, conv_b);
    }
    // 4) cumsum
    k_cumsum<<<BATCH*N_HEADS*NCHUNK, CHUNK>>>(A_log);
    // 5) G = C @ B^T per (b,c)  (fp32 out, as R13)
    {
        dim3 grid(CHUNK/128, CHUNK/128, BATCH*NCHUNK);
        gemm_h<<<grid, 256, GSMEM>>>(bch + D_STATE, 2*D_STATE, (long)CHUNK*2*D_STATE,
                              bch,           2*D_STATE, (long)CHUNK*2*D_STATE,
                              Gp, CHUNK, (long)CHUNK*CHUNK,
                              CHUNK, CHUNK, D_STATE, nullptr);
    }
    // 6) preps
    {
        dim3 grid(NBCH, CHUNK/64);
        k_prep_lg<<<grid, 256>>>();
    }
    k_prep_bc<<<NBCH, 256>>>();
    // 7) Y_diag (tensor)
    {
        dim3 grid(NBCH, CHUNK/128);
        k_ydiag2<<<grid, 256>>>();
    }
    // 8) states (tensor)
    k_states2<<<NBCH, 256>>>();
    // 9) inter-chunk recurrence -> Sin fp16 (full-chip)
    {
        dim3 grid(BATCH*N_HEADS, 8);
        k_chunkrec<<<grid, 256>>>();
    }
    // 10) Y_off += (tensor)
    {
        dim3 grid(NBCH, CHUNK/128);
        k_yoff2<<<grid, 256>>>();
    }
    // 11) gate + D*x + RMSNorm -> fp16
    k_gatenorm<<<BATCH*SEQ, 256>>>(norm_w, Dv);
    // 12) out_proj
    {
        dim3 grid(DIM/128, M/128, 1);
        gemm_h<<<grid, 256, GSMEM>>>(yh, D_INNER, 0, wouth, D_INNER, 0,
                              out, DIM, 0, M, DIM, D_INNER, out_proj_b);
    }
}

// round 16
// speedup vs baseline: 1.4548x; 1.0051x over previous
#include <cuda_runtime.h>
#include <cuda_fp16.h>
#include <math.h>
#include <stdint.h>

#define BATCH   2
#define SEQ     2048
#define DIM     2048
#define D_INNER 4096
#define D_STATE 128
#define N_HEADS 32
#define HEADDIM 128
#define D_CONV  4
#define CHUNK   256
#define NCHUNK  (SEQ/CHUNK)                       /* 8  */
#define NBCH    (BATCH*NCHUNK*N_HEADS)            /* 512 */
#define CONV_DIM (D_INNER + 2*D_STATE)            /* 4352 */
#define D_IN_PROJ (2*D_INNER + 2*D_STATE + N_HEADS) /* 8480 */
#define EPS 1e-5f

// ---------------- scratch (device globals, no allocation) ----------------
__device__ float g_zxbcdt[(size_t)BATCH*SEQ*D_IN_PROJ];
__device__ float g_xBC  [(size_t)BATCH*SEQ*CONV_DIM];
__device__ float g_dt   [(size_t)BATCH*SEQ*N_HEADS];
__device__ float g_dAcum[(size_t)BATCH*N_HEADS*SEQ];
__device__ __half g_G   [(size_t)BATCH*NCHUNK*CHUNK*CHUNK];   // fp16
__device__ float g_states[(size_t)NBCH*HEADDIM*D_STATE];
__device__ float g_y    [(size_t)BATCH*SEQ*D_INNER];
// fp16 operand mirrors
__device__ __half g_in_h  [(size_t)BATCH*SEQ*DIM];
__device__ __half g_win_h [(size_t)D_IN_PROJ*DIM];
__device__ __half g_wout_h[(size_t)DIM*D_INNER];
__device__ __half g_y_h   [(size_t)BATCH*SEQ*D_INNER];
__device__ __half g_bc_h  [(size_t)BATCH*SEQ*2*D_STATE];
// fp16 scan operands
__device__ __half g_xdt_h [(size_t)BATCH*SEQ*D_INNER];
__device__ __half g_LG    [(size_t)NBCH*CHUNK*CHUNK];
__device__ __half g_Bdec  [(size_t)NBCH*CHUNK*D_STATE];
__device__ __half g_Cexp  [(size_t)NBCH*CHUNK*D_STATE];
__device__ __half g_sin_h [(size_t)NBCH*HEADDIM*D_STATE];

__device__ __forceinline__ void cp16(uint32_t dst, const void* src, bool pred) {
    asm volatile("cp.async.cg.shared.global [%0], [%1], 16, %2;"
                 :: "r"(dst), "l"(src), "r"(pred ? 16 : 0));
}
__device__ __forceinline__ void ldsm4(uint32_t* r, uint32_t addr) {
    asm volatile("ldmatrix.sync.aligned.m8n8.x4.shared.b16 {%0,%1,%2,%3}, [%4];"
        : "=r"(r[0]), "=r"(r[1]), "=r"(r[2]), "=r"(r[3]) : "r"(addr));
}
// fast exp on FMA pipe: exp(x) for x<=0
__device__ __forceinline__ float fexp(float x) {
    float t = x * 1.4426950408889634f;
    t = fmaxf(t, -25.f);
    float fi = floorf(t);
    float f = t - fi;
    float p = 1.f + f*(0.69314718f + f*(0.24022651f + f*(0.05550411f
            + f*(0.00961813f + f*0.00133336f))));
    return p * __int_as_float(((int)fi + 127) << 23);
}

#define MMA16(acc, af, bf)                                                   \
    asm volatile(                                                            \
        "mma.sync.aligned.m16n8k16.row.col.f32.f16.f16.f32 "                 \
        "{%0,%1,%2,%3}, {%4,%5,%6,%7}, {%8,%9}, {%0,%1,%2,%3};"              \
        : "+f"(acc[0]), "+f"(acc[1]), "+f"(acc[2]), "+f"(acc[3])             \
        : "r"(af[0]), "r"(af[1]), "r"(af[2]), "r"(af[3]),                    \
          "r"(bf[0]), "r"(bf[1]))

// ================== fp16 mma.sync batched NT GEMM (fp32 out) ==============
// (verbatim Round-13 winning version)
#define GSTG (128*64*2)
#define GSMEM (6*GSTG)
__global__ __launch_bounds__(256, 2)
void gemm_h(const __half* __restrict__ A, long lda, long sA,
            const __half* __restrict__ W, long ldb, long sB,
            float* __restrict__ C, long ldc, long sC,
            int M, int N, int K, const float* __restrict__ bias)
{
    extern __shared__ char smem[];
    int bz = blockIdx.z;
    const __half* Ab = A + (long)bz * sA;
    const __half* Wb = W + (long)bz * sB;
    float*        Cb = C + (long)bz * sC;
    int bm = blockIdx.y * 128, bn = blockIdx.x * 128;
    int tid  = threadIdx.x;
    int warp = tid >> 5, lane = tid & 31;
    int wm = warp >> 2, wn = warp & 3;
    int g  = lane >> 2, t4 = lane & 3;

    uint32_t sAu = (uint32_t)__cvta_generic_to_shared(smem);
    uint32_t sBu = sAu + 3*GSTG;

    int arow = lane & 15;
    int achk = lane >> 4;
    int brow = ((lane >> 4) << 3) + (lane & 7);
    int bchk = (lane >> 3) & 1;

    float acc[4][4][4];
    #pragma unroll
    for (int i = 0; i < 4; i++)
        #pragma unroll
        for (int j = 0; j < 4; j++)
            #pragma unroll
            for (int q = 0; q < 4; q++) acc[i][j][q] = 0.f;

    const int KT = K / 64;

    #define LOADTILE(st, k0)                                                  \
    do {                                                                      \
        _Pragma("unroll")                                                     \
        for (int it = 0; it < 4; it++) {                                      \
            int idx = tid + it*256;                                           \
            int row = idx >> 3, c8 = idx & 7;                                 \
            int sc = c8 ^ (row & 7);                                          \
            cp16(sAu + (st)*GSTG + row*128 + sc*16,                           \
                 &Ab[(long)(bm+row)*lda + (k0) + c8*8], true);                \
        }                                                                     \
        _Pragma("unroll")                                                     \
        for (int it = 0; it < 4; it++) {                                      \
            int idx = tid + it*256;                                           \
            int row = idx >> 3, c8 = idx & 7;                                 \
            int sc = c8 ^ (row & 7);                                          \
            int gn = bn + row; bool p = gn < N;                               \
            cp16(sBu + (st)*GSTG + row*128 + sc*16,                           \
                 &Wb[(long)(p ? gn : 0)*ldb + (k0) + c8*8], p);               \
        }                                                                     \
    } while (0)

    LOADTILE(0, 0);
    asm volatile("cp.async.commit_group;");
    if (KT > 1) LOADTILE(1, 64);
    asm volatile("cp.async.commit_group;");

    for (int kt = 0; kt < KT; kt++) {
        asm volatile("cp.async.wait_group 1;" ::: "memory");
        __syncthreads();
        if (kt + 2 < KT) LOADTILE((kt+2) % 3, (kt+2)*64);
        asm volatile("cp.async.commit_group;");

        int st = kt % 3;
        #pragma unroll
        for (int ks = 0; ks < 4; ks++) {
            uint32_t af[4][4], bf[4][2];
            #pragma unroll
            for (int mt = 0; mt < 4; mt++) {
                int r = wm*64 + mt*16 + arow;
                int chk = (ks*2 + achk) ^ (r & 7);
                ldsm4(af[mt], sAu + st*GSTG + r*128 + chk*16);
            }
            #pragma unroll
            for (int np = 0; np < 2; np++) {
                int r = wn*32 + np*16 + brow;
                int chk = (ks*2 + bchk) ^ (r & 7);
                uint32_t t[4];
                ldsm4(t, sBu + st*GSTG + r*128 + chk*16);
                bf[np*2  ][0] = t[0]; bf[np*2  ][1] = t[1];
                bf[np*2+1][0] = t[2]; bf[np*2+1][1] = t[3];
            }
            #pragma unroll
            for (int mt = 0; mt < 4; mt++)
                #pragma unroll
                for (int nt = 0; nt < 4; nt++)
                    MMA16(acc[mt][nt], af[mt], bf[nt]);
        }
        __syncthreads();
    }
    #undef LOADTILE

    #pragma unroll
    for (int mt = 0; mt < 4; mt++) {
        int row0 = bm + wm*64 + mt*16 + g;
        #pragma unroll
        for (int nt = 0; nt < 4; nt++) {
            int col0 = bn + wn*32 + nt*8 + 2*t4;
            if (col0 < N) {
                float b0 = bias ? bias[col0] : 0.f;
                Cb[(long)row0*ldc + col0] = acc[mt][nt][0] + b0;
                Cb[(long)(row0+8)*ldc + col0] = acc[mt][nt][2] + b0;
            }
            if (col0+1 < N) {
                float b1 = bias ? bias[col0+1] : 0.f;
                Cb[(long)row0*ldc + col0+1] = acc[mt][nt][1] + b1;
                Cb[(long)(row0+8)*ldc + col0+1] = acc[mt][nt][3] + b1;
            }
        }
    }
}

// ====== clone with fp16 output (used only for the small G GEMM) ===========
__global__ __launch_bounds__(256, 2)
void gemm_hh(const __half* __restrict__ A, long lda, long sA,
             const __half* __restrict__ W, long ldb, long sB,
             __half* __restrict__ C, long ldc, long sC,
             int M, int N, int K)
{
    extern __shared__ char smem[];
    int bz = blockIdx.z;
    const __half* Ab = A + (long)bz * sA;
    const __half* Wb = W + (long)bz * sB;
    __half*       Cb = C + (long)bz * sC;
    int bm = blockIdx.y * 128, bn = blockIdx.x * 128;
    int tid  = threadIdx.x;
    int warp = tid >> 5, lane = tid & 31;
    int wm = warp >> 2, wn = warp & 3;
    int g  = lane >> 2, t4 = lane & 3;

    uint32_t sAu = (uint32_t)__cvta_generic_to_shared(smem);
    uint32_t sBu = sAu + 3*GSTG;

    int arow = lane & 15;
    int achk = lane >> 4;
    int brow = ((lane >> 4) << 3) + (lane & 7);
    int bchk = (lane >> 3) & 1;

    float acc[4][4][4];
    #pragma unroll
    for (int i = 0; i < 4; i++)
        #pragma unroll
        for (int j = 0; j < 4; j++)
            #pragma unroll
            for (int q = 0; q < 4; q++) acc[i][j][q] = 0.f;

    const int KT = K / 64;

    #define LOADTILE(st, k0)                                                  \
    do {                                                                      \
        _Pragma("unroll")                                                     \
        for (int it = 0; it < 4; it++) {                                      \
            int idx = tid + it*256;                                           \
            int row = idx >> 3, c8 = idx & 7;                                 \
            int sc = c8 ^ (row & 7);                                          \
            cp16(sAu + (st)*GSTG + row*128 + sc*16,                           \
                 &Ab[(long)(bm+row)*lda + (k0) + c8*8], true);                \
        }                                                                     \
        _Pragma("unroll")                                                     \
        for (int it = 0; it < 4; it++) {                                      \
            int idx = tid + it*256;                                           \
            int row = idx >> 3, c8 = idx & 7;                                 \
            int sc = c8 ^ (row & 7);                                          \
            int gn = bn + row; bool p = gn < N;                               \
            cp16(sBu + (st)*GSTG + row*128 + sc*16,                           \
                 &Wb[(long)(p ? gn : 0)*ldb + (k0) + c8*8], p);               \
        }                                                                     \
    } while (0)

    LOADTILE(0, 0);
    asm volatile("cp.async.commit_group;");
    if (KT > 1) LOADTILE(1, 64);
    asm volatile("cp.async.commit_group;");

    for (int kt = 0; kt < KT; kt++) {
        asm volatile("cp.async.wait_group 1;" ::: "memory");
        __syncthreads();
        if (kt + 2 < KT) LOADTILE((kt+2) % 3, (kt+2)*64);
        asm volatile("cp.async.commit_group;");

        int st = kt % 3;
        #pragma unroll
        for (int ks = 0; ks < 4; ks++) {
            uint32_t af[4][4], bf[4][2];
            #pragma unroll
            for (int mt = 0; mt < 4; mt++) {
                int r = wm*64 + mt*16 + arow;
                int chk = (ks*2 + achk) ^ (r & 7);
                ldsm4(af[mt], sAu + st*GSTG + r*128 + chk*16);
            }
            #pragma unroll
            for (int np = 0; np < 2; np++) {
                int r = wn*32 + np*16 + brow;
                int chk = (ks*2 + bchk) ^ (r & 7);
                uint32_t t[4];
                ldsm4(t, sBu + st*GSTG + r*128 + chk*16);
                bf[np*2  ][0] = t[0]; bf[np*2  ][1] = t[1];
                bf[np*2+1][0] = t[2]; bf[np*2+1][1] = t[3];
            }
            #pragma unroll
            for (int mt = 0; mt < 4; mt++)
                #pragma unroll
                for (int nt = 0; nt < 4; nt++)
                    MMA16(acc[mt][nt], af[mt], bf[nt]);
        }
        __syncthreads();
    }
    #undef LOADTILE

    #pragma unroll
    for (int mt = 0; mt < 4; mt++) {
        int row0 = bm + wm*64 + mt*16 + g;
        #pragma unroll
        for (int nt = 0; nt < 4; nt++) {
            int col0 = bn + wn*32 + nt*8 + 2*t4;
            if (col0 < N) {
                Cb[(long)row0*ldc + col0]     = __float2half_rn(acc[mt][nt][0]);
                Cb[(long)(row0+8)*ldc + col0] = __float2half_rn(acc[mt][nt][2]);
            }
            if (col0+1 < N) {
                Cb[(long)row0*ldc + col0+1]     = __float2half_rn(acc[mt][nt][1]);
                Cb[(long)(row0+8)*ldc + col0+1] = __float2half_rn(acc[mt][nt][3]);
            }
        }
    }
}

// =============== scan GEMM building blocks (128x128 tile, K-step 32) ======
#define SS 42

struct ZIdx { int b, c, h; };
__device__ __forceinline__ ZIdx zdec(int z) {
    ZIdx r; r.h = z % N_HEADS; int bc = z / N_HEADS;
    r.c = bc % NCHUNK; r.b = bc / NCHUNK; return r;
}

// K-loop accumulating into caller's registers; smem passed in.
template<int STAGEA, int STAGEB>
__device__ __forceinline__ void scan_loop(
    float acc[4][4][4],
    __half (*As)[SS], __half (*Bs)[SS],
    const __half* Ag, long lda,
    const __half* Bg, long ldb,
    int KT)
{
    int tid = threadIdx.x;
    int warp = tid >> 5, lane = tid & 31;
    int wm = warp >> 2, wn = warp & 3;
    int g = lane >> 2, t4 = lane & 3;

    for (int kt = 0; kt < KT; kt++) {
        int k0 = kt * 32;
        if (STAGEA == 0) {
            #pragma unroll
            for (int i = 0; i < 8; i++) {
                int idx = tid + i*256;
                int row = idx >> 4, c2 = (idx & 15) * 2;
                *(__half2*)&As[row][c2] = *(const __half2*)&Ag[(long)row*lda + k0 + c2];
            }
        } else {
            #pragma unroll
            for (int i = 0; i < 8; i++) {
                int idx = tid + i*256;
                int k = idx >> 6, m2 = (idx & 63) * 2;
                __half2 v = *(const __half2*)&Ag[(long)(k0+k)*lda + m2];
                As[m2  ][k] = __low2half(v);
                As[m2+1][k] = __high2half(v);
            }
        }
        if (STAGEB == 0) {
            #pragma unroll
            for (int i = 0; i < 8; i++) {
                int idx = tid + i*256;
                int row = idx >> 4, c2 = (idx & 15) * 2;
                *(__half2*)&Bs[row][c2] = *(const __half2*)&Bg[(long)row*ldb + k0 + c2];
            }
        } else {
            #pragma unroll
            for (int i = 0; i < 8; i++) {
                int idx = tid + i*256;
                int k = idx >> 6, n2 = (idx & 63) * 2;
                __half2 v = *(const __half2*)&Bg[(long)(k0+k)*ldb + n2];
                Bs[n2  ][k] = __low2half(v);
                Bs[n2+1][k] = __high2half(v);
            }
        }
        __syncthreads();
        #pragma unroll
        for (int ks = 0; ks < 2; ks++) {
            int kb = ks * 16;
            uint32_t af[4][4], bf[4][2];
            #pragma unroll
            for (int mt = 0; mt < 4; mt++) {
                int r0 = wm*64 + mt*16 + g;
                af[mt][0] = *(const uint32_t*)&As[r0  ][kb + t4*2    ];
                af[mt][1] = *(const uint32_t*)&As[r0+8][kb + t4*2    ];
                af[mt][2] = *(const uint32_t*)&As[r0  ][kb + t4*2 + 8];
                af[mt][3] = *(const uint32_t*)&As[r0+8][kb + t4*2 + 8];
            }
            #pragma unroll
            for (int nt = 0; nt < 4; nt++) {
                int cc = wn*32 + nt*8 + g;
                bf[nt][0] = *(const uint32_t*)&Bs[cc][kb + t4*2    ];
                bf[nt][1] = *(const uint32_t*)&Bs[cc][kb + t4*2 + 8];
            }
            #pragma unroll
            for (int mt = 0; mt < 4; mt++)
                #pragma unroll
                for (int nt = 0; nt < 4; nt++)
                    MMA16(acc[mt][nt], af[mt], bf[nt]);
        }
        __syncthreads();
    }
}

// fused Y = LG@xdt + Cexp@Sin^T, single store to g_y
__global__ __launch_bounds__(256)
void k_ydiagoff()
{
    __shared__ __half As[128][SS];
    __shared__ __half Bs[128][SS];
    int z = blockIdx.x, bm = blockIdx.y * 128;
    ZIdx zi = zdec(z);
    long brow = (long)zi.b*SEQ + zi.c*CHUNK;
    int tid = threadIdx.x;
    int warp = tid >> 5, lane = tid & 31;
    int wm = warp >> 2, wn = warp & 3;
    int g = lane >> 2, t4 = lane & 3;

    float acc[4][4][4];
    #pragma unroll
    for (int i = 0; i < 4; i++)
        #pragma unroll
        for (int j = 0; j < 4; j++)
            #pragma unroll
            for (int q = 0; q < 4; q++) acc[i][j][q] = 0.f;

    // part 1: Y_diag = LG @ xdt  (A direct, B transposed-stage)
    scan_loop<0,1>(acc, As, Bs,
                   g_LG + (long)z*CHUNK*CHUNK + (long)bm*CHUNK, CHUNK,
                   g_xdt_h + brow*D_INNER + zi.h*HEADDIM, D_INNER,
                   (bm + 128) / 32);
    // part 2: Y_off += Cexp @ Sin^T  (both direct)
    scan_loop<0,0>(acc, As, Bs,
                   g_Cexp + (long)z*CHUNK*D_STATE + (long)bm*D_STATE, D_STATE,
                   g_sin_h + (long)z*HEADDIM*D_STATE, D_STATE,
                   D_STATE/32);

    float* Cg = g_y + (brow + bm)*D_INNER + zi.h*HEADDIM;
    #pragma unroll
    for (int mt = 0; mt < 4; mt++) {
        int row0 = wm*64 + mt*16 + g;
        #pragma unroll
        for (int nt = 0; nt < 4; nt++) {
            int col0 = wn*32 + nt*8 + 2*t4;
            Cg[(long)row0*D_INNER + col0  ] = acc[mt][nt][0];
            Cg[(long)row0*D_INNER + col0+1] = acc[mt][nt][1];
            Cg[(long)(row0+8)*D_INNER + col0  ] = acc[mt][nt][2];
            Cg[(long)(row0+8)*D_INNER + col0+1] = acc[mt][nt][3];
        }
    }
}

// states: C[p][n] = sum_l xdt[l][p] * Bdec[l][n]
__global__ __launch_bounds__(256)
void k_states2()
{
    __shared__ __half As[128][SS];
    __shared__ __half Bs[128][SS];
    int z = blockIdx.x;
    ZIdx zi = zdec(z);
    long brow = (long)zi.b*SEQ + zi.c*CHUNK;
    int tid = threadIdx.x;
    int warp = tid >> 5, lane = tid & 31;
    int wm = warp >> 2, wn = warp & 3;
    int g = lane >> 2, t4 = lane & 3;

    float acc[4][4][4];
    #pragma unroll
    for (int i = 0; i < 4; i++)
        #pragma unroll
        for (int j = 0; j < 4; j++)
            #pragma unroll
            for (int q = 0; q < 4; q++) acc[i][j][q] = 0.f;

    scan_loop<1,1>(acc, As, Bs,
                   g_xdt_h + brow*D_INNER + zi.h*HEADDIM, D_INNER,
                   g_Bdec + (long)z*CHUNK*D_STATE, D_STATE,
                   CHUNK/32);

    float* Cg = g_states + (long)z*HEADDIM*D_STATE;
    #pragma unroll
    for (int mt = 0; mt < 4; mt++) {
        int row0 = wm*64 + mt*16 + g;
        #pragma unroll
        for (int nt = 0; nt < 4; nt++) {
            int col0 = wn*32 + nt*8 + 2*t4;
            Cg[(long)row0*D_STATE + col0  ] = acc[mt][nt][0];
            Cg[(long)row0*D_STATE + col0+1] = acc[mt][nt][1];
            Cg[(long)(row0+8)*D_STATE + col0  ] = acc[mt][nt][2];
            Cg[(long)(row0+8)*D_STATE + col0+1] = acc[mt][nt][3];
        }
    }
}

// ---------------- prep kernels --------------------------------------------
__global__ __launch_bounds__(256)
void k_prep_lg()
{
    int z = blockIdx.x, lt = blockIdx.y;
    ZIdx zi = zdec(z);
    int bc = z / N_HEADS;
    const float* cum = g_dAcum + ((long)zi.b*N_HEADS + zi.h)*SEQ + zi.c*CHUNK;
    __shared__ float cs[CHUNK];
    if (threadIdx.x < CHUNK) cs[threadIdx.x] = cum[threadIdx.x];
    __syncthreads();
    const __half* G = g_G + (long)bc*CHUNK*CHUNK;
    __half* LG = g_LG + (long)z*CHUNK*CHUNK;
    int tid = threadIdx.x;
    #pragma unroll 4
    for (int j = 0; j < 64; j++) {
        int lin = tid + j*256;
        int l = lt*64 + (lin >> 8);
        int s = lin & 255;
        float v = 0.f;
        if (s <= l) v = __half2float(G[l*CHUNK + s]) * fexp(cs[l] - cs[s]);
        LG[l*CHUNK + s] = __float2half_rn(v);
    }
}

__global__ __launch_bounds__(256)
void k_prep_bc()
{
    int z = blockIdx.x;
    ZIdx zi = zdec(z);
    const float* cum = g_dAcum + ((long)zi.b*N_HEADS + zi.h)*SEQ + zi.c*CHUNK;
    __shared__ float fb[CHUNK], fc[CHUNK];
    if (threadIdx.x < CHUNK) {
        float cl = cum[threadIdx.x];
        fb[threadIdx.x] = fexp(cum[CHUNK-1] - cl);
        fc[threadIdx.x] = fexp(cl);
    }
    __syncthreads();
    long brow = (long)zi.b*SEQ + zi.c*CHUNK;
    __half* Bd = g_Bdec + (long)z*CHUNK*D_STATE;
    __half* Ce = g_Cexp + (long)z*CHUNK*D_STATE;
    int tid = threadIdx.x;
    #pragma unroll 4
    for (int j = 0; j < 128; j++) {
        int lin = tid + j*256;
        int l = lin >> 7, n = lin & 127;
        long bs = brow + l;
        float Bv = __half2float(g_bc_h[bs*(2*D_STATE) + n]);
        float Cv = __half2float(g_bc_h[bs*(2*D_STATE) + D_STATE + n]);
        Bd[lin] = __float2half_rn(Bv * fb[l]);
        Ce[lin] = __float2half_rn(Cv * fc[l]);
    }
}

__global__ __launch_bounds__(256)
void k_tohalf(const float* __restrict__ src, __half* __restrict__ dst, long n2)
{
    long i = (long)blockIdx.x * 256 + threadIdx.x;
    long stride = (long)gridDim.x * 256;
    for (; i < n2; i += stride) {
        float2 v = *reinterpret_cast<const float2*>(src + i*2);
        *reinterpret_cast<__half2*>(dst + i*2) = __floats2half2_rn(v.x, v.y);
    }
}

// ---------------- exact fp32 dt projection + softplus ---------------------
__global__ __launch_bounds__(256)
void k_dtproj(const float* __restrict__ inputs,
              const float* __restrict__ in_proj_w,
              const float* __restrict__ in_proj_b,
              const float* __restrict__ dt_bias)
{
    __shared__ float xs[32][133];
    __shared__ float ws[32][133];
    int t = threadIdx.x;
    long r0 = (long)blockIdx.x * 32;
    int r = t >> 3;
    int hb = (t & 7) * 4;
    const float* Wdt = in_proj_w + (size_t)(D_INNER + CONV_DIM) * DIM;
    float acc[4] = {0.f, 0.f, 0.f, 0.f};
    for (int k0 = 0; k0 < DIM; k0 += 128) {
        #pragma unroll
        for (int i = 0; i < 4; i++) {
            int idx = t + i*256;
            int row = idx >> 5, c4 = (idx & 31) * 4;
            float4 v = *reinterpret_cast<const float4*>(&inputs[(r0+row)*DIM + k0 + c4]);
            xs[row][c4] = v.x; xs[row][c4+1] = v.y; xs[row][c4+2] = v.z; xs[row][c4+3] = v.w;
            float4 w = *reinterpret_cast<const float4*>(&Wdt[(size_t)row*DIM + k0 + c4]);
            ws[row][c4] = w.x; ws[row][c4+1] = w.y; ws[row][c4+2] = w.z; ws[row][c4+3] = w.w;
        }
        __syncthreads();
        #pragma unroll 8
        for (int k = 0; k < 128; k++) {
            float xv = xs[r][k];
            #pragma unroll
            for (int j = 0; j < 4; j++)
                acc[j] = fmaf(xv, ws[hb+j][k], acc[j]);
        }
        __syncthreads();
    }
    #pragma unroll
    for (int j = 0; j < 4; j++) {
        int h = hb + j;
        float x = acc[j] + in_proj_b[D_INNER + CONV_DIM + h] + dt_bias[h];
        g_dt[(r0 + r)*N_HEADS + h] = (x > 20.f) ? x : log1pf(expf(x));
    }
}

// ---------------- tiled conv + SiLU + fused xdt/bc fp16 -------------------
#define CTS 32
__global__ __launch_bounds__(256)
void k_conv_t(const float* __restrict__ conv_w, const float* __restrict__ conv_b)
{
    __shared__ float xs[CTS + 3][256];
    __shared__ float sdt[CTS][2];
    int tid = threadIdx.x;
    int c0 = blockIdx.x * 256;
    int s0 = blockIdx.y * CTS;
    int b  = blockIdx.z;
    int c  = c0 + tid;
    long base = ((long)b*SEQ + s0) * D_IN_PROJ + D_INNER + c;

    #pragma unroll
    for (int i = 0; i < CTS + 3; i++) {
        int sp = s0 - 3 + i;
        xs[i][tid] = (sp >= 0) ? g_zxbcdt[base + (long)(i - 3) * D_IN_PROJ] : 0.f;
    }
    bool isx = (c0 < D_INNER);
    if (isx && tid < CTS*2) {
        int j = tid >> 1, hh = tid & 1;
        sdt[j][hh] = g_dt[((long)b*SEQ + s0 + j)*N_HEADS + (c0 >> 7) + hh];
    }
    __syncthreads();

    float w0 = conv_w[c*D_CONV+0], w1 = conv_w[c*D_CONV+1];
    float w2 = conv_w[c*D_CONV+2], w3 = conv_w[c*D_CONV+3];
    float bsv = conv_b[c];
    int hsel = (tid >> 7) & 1;

    #pragma unroll 4
    for (int j = 0; j < CTS; j++) {
        float acc = bsv;
        acc = fmaf(xs[j  ][tid], w0, acc);
        acc = fmaf(xs[j+1][tid], w1, acc);
        acc = fmaf(xs[j+2][tid], w2, acc);
        acc = fmaf(xs[j+3][tid], w3, acc);
        float v = acc / (1.f + expf(-acc));
        long bs = (long)b*SEQ + s0 + j;
        g_xBC[bs*CONV_DIM + c] = v;
        if (isx) {
            g_xdt_h[bs*D_INNER + c] = __float2half_rn(v * sdt[j][hsel]);
        } else {
            int cc = c - D_INNER;
            if (cc >= 0)
                g_bc_h[bs*(2*D_STATE) + cc] = __float2half_rn(v);
        }
    }
}

// ---------------- chunk-local inclusive cumsum of A*dt --------------------
__global__ __launch_bounds__(CHUNK)
void k_cumsum(const float* __restrict__ A_log)
{
    int bz = blockIdx.x;
    int c = bz % NCHUNK; int bh = bz / NCHUNK;
    int h = bh % N_HEADS; int b = bh / N_HEADS;
    int l = threadIdx.x;
    int sg = c*CHUNK + l;
    float A = -expf(A_log[h]);
    float val = A * g_dt[((long)b*SEQ + sg)*N_HEADS + h];
    __shared__ float buf[CHUNK];
    buf[l] = val; __syncthreads();
    for (int off = 1; off < CHUNK; off <<= 1) {
        float t = (l >= off) ? buf[l-off] : 0.f;
        __syncthreads();
        buf[l] += t;
        __syncthreads();
    }
    g_dAcum[((long)b*N_HEADS + h)*SEQ + sg] = buf[l];
}

// ---------------- inter-chunk recurrence (-> Sin fp16), full-chip ---------
__global__ __launch_bounds__(256)
void k_chunkrec()
{
    int bh = blockIdx.x;
    int h = bh % N_HEADS; int b = bh / N_HEADS;
    const float* cum = g_dAcum + (long)bh*SEQ;
    float csum[NCHUNK];
    #pragma unroll
    for (int c = 0; c < NCHUNK; c++) csum[c] = expf(cum[c*CHUNK + CHUNK-1]);
    int pn0 = blockIdx.y * (HEADDIM*D_STATE/8);
    #pragma unroll
    for (int j = 0; j < (HEADDIM*D_STATE/8)/256; j++) {
        int pn = pn0 + j*256 + threadIdx.x;
        float carry = 0.f;
        #pragma unroll
        for (int c = 0; c < NCHUNK; c++) {
            long z = ((long)b*NCHUNK + c)*N_HEADS + h;
            long idx = z*HEADDIM*D_STATE + pn;
            g_sin_h[idx] = __float2half_rn(carry);
            carry = carry * csum[c] + g_states[idx];
        }
    }
}

// ---------------- gate (y + D*x) * silu(z) + RMSNorm -> fp16 --------------
__global__ __launch_bounds__(256)
void k_gatenorm(const float* __restrict__ norm_w, const float* __restrict__ Dv)
{
    long row = blockIdx.x;
    const float* zrow = g_zxbcdt + row*D_IN_PROJ;
    const float* xrow = g_xBC + row*CONV_DIM;
    float* yrow = g_y + row*D_INNER;
    __half* yh = g_y_h + row*D_INNER;
    float vals[16];
    float local = 0.f;
    #pragma unroll
    for (int i = 0; i < 16; i++) {
        int d = threadIdx.x + i*256;
        float z = zrow[d];
        float v = (yrow[d] + Dv[d >> 7] * xrow[d]) * (z / (1.f + expf(-z)));
        vals[i] = v;
        local += v * v;
    }
    __shared__ float red[256];
    red[threadIdx.x] = local; __syncthreads();
    for (int off = 128; off > 0; off >>= 1) {
        if (threadIdx.x < off) red[threadIdx.x] += red[threadIdx.x + off];
        __syncthreads();
    }
    float scale = rsqrtf(red[0] / D_INNER + EPS);
    #pragma unroll
    for (int i = 0; i < 16; i++) {
        int d = threadIdx.x + i*256;
        yh[d] = __float2half_rn(vals[i] * scale * norm_w[d]);
    }
}

// --------------------------------------------------------------------------
extern "C" void kernel_launch(void* const* d_in, const int* in_sizes, int n_in,
                              void* d_out, int out_size)
{
    const float* inputs     = (const float*)d_in[0];
    const float* in_proj_w  = (const float*)d_in[1];
    const float* in_proj_b  = (const float*)d_in[2];
    const float* out_proj_w = (const float*)d_in[3];
    const float* out_proj_b = (const float*)d_in[4];
    const float* conv_w     = (const float*)d_in[5];
    const float* conv_b     = (const float*)d_in[6];
    const float* dt_bias    = (const float*)d_in[7];
    const float* A_log      = (const float*)d_in[8];
    const float* Dv         = (const float*)d_in[9];
    const float* norm_w     = (const float*)d_in[10];
    float* out = (float*)d_out;

    float *zx;
    __half *Gp, *inh, *winh, *wouth, *yh, *bch;
    cudaGetSymbolAddress((void**)&zx,    g_zxbcdt);
    cudaGetSymbolAddress((void**)&Gp,    g_G);
    cudaGetSymbolAddress((void**)&inh,   g_in_h);
    cudaGetSymbolAddress((void**)&winh,  g_win_h);
    cudaGetSymbolAddress((void**)&wouth, g_wout_h);
    cudaGetSymbolAddress((void**)&yh,    g_y_h);
    cudaGetSymbolAddress((void**)&bch,   g_bc_h);

    cudaFuncSetAttribute(gemm_h,  cudaFuncAttributeMaxDynamicSharedMemorySize, GSMEM);
    cudaFuncSetAttribute(gemm_hh, cudaFuncAttributeMaxDynamicSharedMemorySize, GSMEM);

    const int M = BATCH * SEQ;     // 4096

    // 0) fp16 mirrors
    k_tohalf<<<2048, 256>>>(inputs,     inh,   (long)M*DIM/2);
    k_tohalf<<<2048, 256>>>(in_proj_w,  winh,  (long)D_IN_PROJ*DIM/2);
    k_tohalf<<<2048, 256>>>(out_proj_w, wouth, (long)DIM*D_INNER/2);

    // 1) in_proj
    {
        dim3 grid((D_IN_PROJ + 127)/128, M/128, 1);
        gemm_h<<<grid, 256, GSMEM>>>(inh, DIM, 0, winh, DIM, 0,
                              zx, D_IN_PROJ, 0, M, D_IN_PROJ, DIM, in_proj_b);
    }
    // 2) exact dt projection (before conv: conv consumes dt)
    k_dtproj<<<M/32, 256>>>(inputs, in_proj_w, in_proj_b, dt_bias);
    // 3) tiled conv + silu, fused xdt/bc fp16 production
    {
        dim3 grid(CONV_DIM/256, SEQ/CTS, BATCH);
        k_conv_t<<<grid, 256>>>(conv_w, conv_b);
    }
    // 4) cumsum
    k_cumsum<<<BATCH*N_HEADS*NCHUNK, CHUNK>>>(A_log);
    // 5) G = C @ B^T per (b,c), fp16 output (separate clone kernel)
    {
        dim3 grid(CHUNK/128, CHUNK/128, BATCH*NCHUNK);
        gemm_hh<<<grid, 256, GSMEM>>>(bch + D_STATE, 2*D_STATE, (long)CHUNK*2*D_STATE,
                              bch,           2*D_STATE, (long)CHUNK*2*D_STATE,
                              Gp, CHUNK, (long)CHUNK*CHUNK,
                              CHUNK, CHUNK, D_STATE);
    }
    // 6) preps
    {
        dim3 grid(NBCH, CHUNK/64);
        k_prep_lg<<<grid, 256>>>();
    }
    k_prep_bc<<<NBCH, 256>>>();
    // 7) states (tensor)
    k_states2<<<NBCH, 256>>>();
    // 8) inter-chunk recurrence -> Sin fp16 (full-chip)
    {
        dim3 grid(BATCH*N_HEADS, 8);
        k_chunkrec<<<grid, 256>>>();
    }
    // 9) fused Y_diag + Y_off (tensor), single g_y store
    {
        dim3 grid(NBCH, CHUNK/128);
        k_ydiagoff<<<grid, 256>>>();
    }
    // 10) gate + D*x + RMSNorm -> fp16
    k_gatenorm<<<BATCH*SEQ, 256>>>(norm_w, Dv);
    // 11) out_proj
    {
        dim3 grid(DIM/128, M/128, 1);
        gemm_h<<<grid, 256, GSMEM>>>(yh, D_INNER, 0, wouth, D_INNER, 0,
                              out, DIM, 0, M, DIM, D_INNER, out_proj_b);
    }
}

// round 17
// speedup vs baseline: 1.5748x; 1.0824x over previous
#include <cuda_runtime.h>
#include <cuda_fp16.h>
#include <math.h>
#include <stdint.h>

#define BATCH   2
#define SEQ     2048
#define DIM     2048
#define D_INNER 4096
#define D_STATE 128
#define N_HEADS 32
#define HEADDIM 128
#define D_CONV  4
#define CHUNK   256
#define NCHUNK  (SEQ/CHUNK)                       /* 8  */
#define NBCH    (BATCH*NCHUNK*N_HEADS)            /* 512 */
#define CONV_DIM (D_INNER + 2*D_STATE)            /* 4352 */
#define D_IN_PROJ (2*D_INNER + 2*D_STATE + N_HEADS) /* 8480 */
#define EPS 1e-5f

// ---------------- scratch (device globals, no allocation) ----------------
__device__ float g_zxbcdt[(size_t)BATCH*SEQ*D_IN_PROJ];
__device__ float g_xBC  [(size_t)BATCH*SEQ*CONV_DIM];
__device__ float g_dt   [(size_t)BATCH*SEQ*N_HEADS];
__device__ float g_dAcum[(size_t)BATCH*N_HEADS*SEQ];
__device__ __half g_G   [(size_t)BATCH*NCHUNK*CHUNK*CHUNK];   // fp16
__device__ float g_states[(size_t)NBCH*HEADDIM*D_STATE];
__device__ float g_y    [(size_t)BATCH*SEQ*D_INNER];
// fp16 operand mirrors
__device__ __half g_in_h  [(size_t)BATCH*SEQ*DIM];
__device__ __half g_win_h [(size_t)D_IN_PROJ*DIM];
__device__ __half g_wout_h[(size_t)DIM*D_INNER];
__device__ __half g_y_h   [(size_t)BATCH*SEQ*D_INNER];
__device__ __half g_bc_h  [(size_t)BATCH*SEQ*2*D_STATE];
// fp16 scan operands
__device__ __half g_xdt_h [(size_t)BATCH*SEQ*D_INNER];
__device__ __half g_LG    [(size_t)NBCH*CHUNK*CHUNK];
__device__ __half g_sin_h [(size_t)NBCH*HEADDIM*D_STATE];

__device__ __forceinline__ void cp16(uint32_t dst, const void* src, bool pred) {
    asm volatile("cp.async.cg.shared.global [%0], [%1], 16, %2;"
                 :: "r"(dst), "l"(src), "r"(pred ? 16 : 0));
}
__device__ __forceinline__ void ldsm4(uint32_t* r, uint32_t addr) {
    asm volatile("ldmatrix.sync.aligned.m8n8.x4.shared.b16 {%0,%1,%2,%3}, [%4];"
        : "=r"(r[0]), "=r"(r[1]), "=r"(r[2]), "=r"(r[3]) : "r"(addr));
}
// fast exp on FMA pipe: exp(x) for x<=0
__device__ __forceinline__ float fexp(float x) {
    float t = x * 1.4426950408889634f;
    t = fmaxf(t, -25.f);
    float fi = floorf(t);
    float f = t - fi;
    float p = 1.f + f*(0.69314718f + f*(0.24022651f + f*(0.05550411f
            + f*(0.00961813f + f*0.00133336f))));
    return p * __int_as_float(((int)fi + 127) << 23);
}

#define MMA16(acc, af, bf)                                                   \
    asm volatile(                                                            \
        "mma.sync.aligned.m16n8k16.row.col.f32.f16.f16.f32 "                 \
        "{%0,%1,%2,%3}, {%4,%5,%6,%7}, {%8,%9}, {%0,%1,%2,%3};"              \
        : "+f"(acc[0]), "+f"(acc[1]), "+f"(acc[2]), "+f"(acc[3])             \
        : "r"(af[0]), "r"(af[1]), "r"(af[2]), "r"(af[3]),                    \
          "r"(bf[0]), "r"(bf[1]))

// ================== fp16 mma.sync batched NT GEMM (fp32 out) ==============
// (verbatim Round-13 winning version)
#define GSTG (128*64*2)
#define GSMEM (6*GSTG)
__global__ __launch_bounds__(256, 2)
void gemm_h(const __half* __restrict__ A, long lda, long sA,
            const __half* __restrict__ W, long ldb, long sB,
            float* __restrict__ C, long ldc, long sC,
            int M, int N, int K, const float* __restrict__ bias)
{
    extern __shared__ char smem[];
    int bz = blockIdx.z;
    const __half* Ab = A + (long)bz * sA;
    const __half* Wb = W + (long)bz * sB;
    float*        Cb = C + (long)bz * sC;
    int bm = blockIdx.y * 128, bn = blockIdx.x * 128;
    int tid  = threadIdx.x;
    int warp = tid >> 5, lane = tid & 31;
    int wm = warp >> 2, wn = warp & 3;
    int g  = lane >> 2, t4 = lane & 3;

    uint32_t sAu = (uint32_t)__cvta_generic_to_shared(smem);
    uint32_t sBu = sAu + 3*GSTG;

    int arow = lane & 15;
    int achk = lane >> 4;
    int brow = ((lane >> 4) << 3) + (lane & 7);
    int bchk = (lane >> 3) & 1;

    float acc[4][4][4];
    #pragma unroll
    for (int i = 0; i < 4; i++)
        #pragma unroll
        for (int j = 0; j < 4; j++)
            #pragma unroll
            for (int q = 0; q < 4; q++) acc[i][j][q] = 0.f;

    const int KT = K / 64;

    #define LOADTILE(st, k0)                                                  \
    do {                                                                      \
        _Pragma("unroll")                                                     \
        for (int it = 0; it < 4; it++) {                                      \
            int idx = tid + it*256;                                           \
            int row = idx >> 3, c8 = idx & 7;                                 \
            int sc = c8 ^ (row & 7);                                          \
            cp16(sAu + (st)*GSTG + row*128 + sc*16,                           \
                 &Ab[(long)(bm+row)*lda + (k0) + c8*8], true);                \
        }                                                                     \
        _Pragma("unroll")                                                     \
        for (int it = 0; it < 4; it++) {                                      \
            int idx = tid + it*256;                                           \
            int row = idx >> 3, c8 = idx & 7;                                 \
            int sc = c8 ^ (row & 7);                                          \
            int gn = bn + row; bool p = gn < N;                               \
            cp16(sBu + (st)*GSTG + row*128 + sc*16,                           \
                 &Wb[(long)(p ? gn : 0)*ldb + (k0) + c8*8], p);               \
        }                                                                     \
    } while (0)

    LOADTILE(0, 0);
    asm volatile("cp.async.commit_group;");
    if (KT > 1) LOADTILE(1, 64);
    asm volatile("cp.async.commit_group;");

    for (int kt = 0; kt < KT; kt++) {
        asm volatile("cp.async.wait_group 1;" ::: "memory");
        __syncthreads();
        if (kt + 2 < KT) LOADTILE((kt+2) % 3, (kt+2)*64);
        asm volatile("cp.async.commit_group;");

        int st = kt % 3;
        #pragma unroll
        for (int ks = 0; ks < 4; ks++) {
            uint32_t af[4][4], bf[4][2];
            #pragma unroll
            for (int mt = 0; mt < 4; mt++) {
                int r = wm*64 + mt*16 + arow;
                int chk = (ks*2 + achk) ^ (r & 7);
                ldsm4(af[mt], sAu + st*GSTG + r*128 + chk*16);
            }
            #pragma unroll
            for (int np = 0; np < 2; np++) {
                int r = wn*32 + np*16 + brow;
                int chk = (ks*2 + bchk) ^ (r & 7);
                uint32_t t[4];
                ldsm4(t, sBu + st*GSTG + r*128 + chk*16);
                bf[np*2  ][0] = t[0]; bf[np*2  ][1] = t[1];
                bf[np*2+1][0] = t[2]; bf[np*2+1][1] = t[3];
            }
            #pragma unroll
            for (int mt = 0; mt < 4; mt++)
                #pragma unroll
                for (int nt = 0; nt < 4; nt++)
                    MMA16(acc[mt][nt], af[mt], bf[nt]);
        }
        __syncthreads();
    }
    #undef LOADTILE

    #pragma unroll
    for (int mt = 0; mt < 4; mt++) {
        int row0 = bm + wm*64 + mt*16 + g;
        #pragma unroll
        for (int nt = 0; nt < 4; nt++) {
            int col0 = bn + wn*32 + nt*8 + 2*t4;
            if (col0 < N) {
                float b0 = bias ? bias[col0] : 0.f;
                Cb[(long)row0*ldc + col0] = acc[mt][nt][0] + b0;
                Cb[(long)(row0+8)*ldc + col0] = acc[mt][nt][2] + b0;
            }
            if (col0+1 < N) {
                float b1 = bias ? bias[col0+1] : 0.f;
                Cb[(long)row0*ldc + col0+1] = acc[mt][nt][1] + b1;
                Cb[(long)(row0+8)*ldc + col0+1] = acc[mt][nt][3] + b1;
            }
        }
    }
}

// ====== clone with fp16 output (used only for the small G GEMM) ===========
__global__ __launch_bounds__(256, 2)
void gemm_hh(const __half* __restrict__ A, long lda, long sA,
             const __half* __restrict__ W, long ldb, long sB,
             __half* __restrict__ C, long ldc, long sC,
             int M, int N, int K)
{
    extern __shared__ char smem[];
    int bz = blockIdx.z;
    const __half* Ab = A + (long)bz * sA;
    const __half* Wb = W + (long)bz * sB;
    __half*       Cb = C + (long)bz * sC;
    int bm = blockIdx.y * 128, bn = blockIdx.x * 128;
    int tid  = threadIdx.x;
    int warp = tid >> 5, lane = tid & 31;
    int wm = warp >> 2, wn = warp & 3;
    int g  = lane >> 2, t4 = lane & 3;

    uint32_t sAu = (uint32_t)__cvta_generic_to_shared(smem);
    uint32_t sBu = sAu + 3*GSTG;

    int arow = lane & 15;
    int achk = lane >> 4;
    int brow = ((lane >> 4) << 3) + (lane & 7);
    int bchk = (lane >> 3) & 1;

    float acc[4][4][4];
    #pragma unroll
    for (int i = 0; i < 4; i++)
        #pragma unroll
        for (int j = 0; j < 4; j++)
            #pragma unroll
            for (int q = 0; q < 4; q++) acc[i][j][q] = 0.f;

    const int KT = K / 64;

    #define LOADTILE(st, k0)                                                  \
    do {                                                                      \
        _Pragma("unroll")                                                     \
        for (int it = 0; it < 4; it++) {                                      \
            int idx = tid + it*256;                                           \
            int row = idx >> 3, c8 = idx & 7;                                 \
            int sc = c8 ^ (row & 7);                                          \
            cp16(sAu + (st)*GSTG + row*128 + sc*16,                           \
                 &Ab[(long)(bm+row)*lda + (k0) + c8*8], true);                \
        }                                                                     \
        _Pragma("unroll")                                                     \
        for (int it = 0; it < 4; it++) {                                      \
            int idx = tid + it*256;                                           \
            int row = idx >> 3, c8 = idx & 7;                                 \
            int sc = c8 ^ (row & 7);                                          \
            int gn = bn + row; bool p = gn < N;                               \
            cp16(sBu + (st)*GSTG + row*128 + sc*16,                           \
                 &Wb[(long)(p ? gn : 0)*ldb + (k0) + c8*8], p);               \
        }                                                                     \
    } while (0)

    LOADTILE(0, 0);
    asm volatile("cp.async.commit_group;");
    if (KT > 1) LOADTILE(1, 64);
    asm volatile("cp.async.commit_group;");

    for (int kt = 0; kt < KT; kt++) {
        asm volatile("cp.async.wait_group 1;" ::: "memory");
        __syncthreads();
        if (kt + 2 < KT) LOADTILE((kt+2) % 3, (kt+2)*64);
        asm volatile("cp.async.commit_group;");

        int st = kt % 3;
        #pragma unroll
        for (int ks = 0; ks < 4; ks++) {
            uint32_t af[4][4], bf[4][2];
            #pragma unroll
            for (int mt = 0; mt < 4; mt++) {
                int r = wm*64 + mt*16 + arow;
                int chk = (ks*2 + achk) ^ (r & 7);
                ldsm4(af[mt], sAu + st*GSTG + r*128 + chk*16);
            }
            #pragma unroll
            for (int np = 0; np < 2; np++) {
                int r = wn*32 + np*16 + brow;
                int chk = (ks*2 + bchk) ^ (r & 7);
                uint32_t t[4];
                ldsm4(t, sBu + st*GSTG + r*128 + chk*16);
                bf[np*2  ][0] = t[0]; bf[np*2  ][1] = t[1];
                bf[np*2+1][0] = t[2]; bf[np*2+1][1] = t[3];
            }
            #pragma unroll
            for (int mt = 0; mt < 4; mt++)
                #pragma unroll
                for (int nt = 0; nt < 4; nt++)
                    MMA16(acc[mt][nt], af[mt], bf[nt]);
        }
        __syncthreads();
    }
    #undef LOADTILE

    #pragma unroll
    for (int mt = 0; mt < 4; mt++) {
        int row0 = bm + wm*64 + mt*16 + g;
        #pragma unroll
        for (int nt = 0; nt < 4; nt++) {
            int col0 = bn + wn*32 + nt*8 + 2*t4;
            if (col0 < N) {
                Cb[(long)row0*ldc + col0]     = __float2half_rn(acc[mt][nt][0]);
                Cb[(long)(row0+8)*ldc + col0] = __float2half_rn(acc[mt][nt][2]);
            }
            if (col0+1 < N) {
                Cb[(long)row0*ldc + col0+1]     = __float2half_rn(acc[mt][nt][1]);
                Cb[(long)(row0+8)*ldc + col0+1] = __float2half_rn(acc[mt][nt][3]);
            }
        }
    }
}

// =============== scan GEMM building blocks (128x128 tile, K-step 32) ======
#define SS 42

struct ZIdx { int b, c, h; };
__device__ __forceinline__ ZIdx zdec(int z) {
    ZIdx r; r.h = z % N_HEADS; int bc = z / N_HEADS;
    r.c = bc % NCHUNK; r.b = bc / NCHUNK; return r;
}

// K-loop accumulating into caller's registers; smem passed in.
template<int STAGEA, int STAGEB>
__device__ __forceinline__ void scan_loop(
    float acc[4][4][4],
    __half (*As)[SS], __half (*Bs)[SS],
    const __half* Ag, long lda,
    const __half* Bg, long ldb,
    int KT)
{
    int tid = threadIdx.x;
    int warp = tid >> 5, lane = tid & 31;
    int wm = warp >> 2, wn = warp & 3;
    int g = lane >> 2, t4 = lane & 3;

    for (int kt = 0; kt < KT; kt++) {
        int k0 = kt * 32;
        if (STAGEA == 0) {
            #pragma unroll
            for (int i = 0; i < 8; i++) {
                int idx = tid + i*256;
                int row = idx >> 4, c2 = (idx & 15) * 2;
                *(__half2*)&As[row][c2] = *(const __half2*)&Ag[(long)row*lda + k0 + c2];
            }
        } else {
            #pragma unroll
            for (int i = 0; i < 8; i++) {
                int idx = tid + i*256;
                int k = idx >> 6, m2 = (idx & 63) * 2;
                __half2 v = *(const __half2*)&Ag[(long)(k0+k)*lda + m2];
                As[m2  ][k] = __low2half(v);
                As[m2+1][k] = __high2half(v);
            }
        }
        if (STAGEB == 0) {
            #pragma unroll
            for (int i = 0; i < 8; i++) {
                int idx = tid + i*256;
                int row = idx >> 4, c2 = (idx & 15) * 2;
                *(__half2*)&Bs[row][c2] = *(const __half2*)&Bg[(long)row*ldb + k0 + c2];
            }
        } else {
            #pragma unroll
            for (int i = 0; i < 8; i++) {
                int idx = tid + i*256;
                int k = idx >> 6, n2 = (idx & 63) * 2;
                __half2 v = *(const __half2*)&Bg[(long)(k0+k)*ldb + n2];
                Bs[n2  ][k] = __low2half(v);
                Bs[n2+1][k] = __high2half(v);
            }
        }
        __syncthreads();
        #pragma unroll
        for (int ks = 0; ks < 2; ks++) {
            int kb = ks * 16;
            uint32_t af[4][4], bf[4][2];
            #pragma unroll
            for (int mt = 0; mt < 4; mt++) {
                int r0 = wm*64 + mt*16 + g;
                af[mt][0] = *(const uint32_t*)&As[r0  ][kb + t4*2    ];
                af[mt][1] = *(const uint32_t*)&As[r0+8][kb + t4*2    ];
                af[mt][2] = *(const uint32_t*)&As[r0  ][kb + t4*2 + 8];
                af[mt][3] = *(const uint32_t*)&As[r0+8][kb + t4*2 + 8];
            }
            #pragma unroll
            for (int nt = 0; nt < 4; nt++) {
                int cc = wn*32 + nt*8 + g;
                bf[nt][0] = *(const uint32_t*)&Bs[cc][kb + t4*2    ];
                bf[nt][1] = *(const uint32_t*)&Bs[cc][kb + t4*2 + 8];
            }
            #pragma unroll
            for (int mt = 0; mt < 4; mt++)
                #pragma unroll
                for (int nt = 0; nt < 4; nt++)
                    MMA16(acc[mt][nt], af[mt], bf[nt]);
        }
        __syncthreads();
    }
}

// fused Y = LG@xdt + diag(exp(cum)) * (C@Sin^T), single store to g_y
__global__ __launch_bounds__(256)
void k_ydiagoff()
{
    __shared__ __half As[128][SS];
    __shared__ __half Bs[128][SS];
    __shared__ float cs[128];
    int z = blockIdx.x, bm = blockIdx.y * 128;
    ZIdx zi = zdec(z);
    long brow = (long)zi.b*SEQ + zi.c*CHUNK;
    int tid = threadIdx.x;
    int warp = tid >> 5, lane = tid & 31;
    int wm = warp >> 2, wn = warp & 3;
    int g = lane >> 2, t4 = lane & 3;

    const float* cum = g_dAcum + ((long)zi.b*N_HEADS + zi.h)*SEQ + zi.c*CHUNK;
    if (tid < 128) cs[tid] = cum[bm + tid];

    float acc[4][4][4];
    #pragma unroll
    for (int i = 0; i < 4; i++)
        #pragma unroll
        for (int j = 0; j < 4; j++)
            #pragma unroll
            for (int q = 0; q < 4; q++) acc[i][j][q] = 0.f;

    // part A: C @ Sin^T  (C plain from bc_h; both direct-staged)
    scan_loop<0,0>(acc, As, Bs,
                   g_bc_h + (brow + bm)*(2*D_STATE) + D_STATE, 2*D_STATE,
                   g_sin_h + (long)z*HEADDIM*D_STATE, D_STATE,
                   D_STATE/32);
    // scale rows by exp(cum_l)  (fp32, on accumulators)
    #pragma unroll
    for (int mt = 0; mt < 4; mt++) {
        int r0 = wm*64 + mt*16 + g;
        float f0 = fexp(cs[r0]);
        float f1 = fexp(cs[r0 + 8]);
        #pragma unroll
        for (int nt = 0; nt < 4; nt++) {
            acc[mt][nt][0] *= f0; acc[mt][nt][1] *= f0;
            acc[mt][nt][2] *= f1; acc[mt][nt][3] *= f1;
        }
    }
    // part B: += LG @ xdt  (A direct, B transposed-stage)
    scan_loop<0,1>(acc, As, Bs,
                   g_LG + (long)z*CHUNK*CHUNK + (long)bm*CHUNK, CHUNK,
                   g_xdt_h + brow*D_INNER + zi.h*HEADDIM, D_INNER,
                   (bm + 128) / 32);

    float* Cg = g_y + (brow + bm)*D_INNER + zi.h*HEADDIM;
    #pragma unroll
    for (int mt = 0; mt < 4; mt++) {
        int row0 = wm*64 + mt*16 + g;
        #pragma unroll
        for (int nt = 0; nt < 4; nt++) {
            int col0 = wn*32 + nt*8 + 2*t4;
            Cg[(long)row0*D_INNER + col0  ] = acc[mt][nt][0];
            Cg[(long)row0*D_INNER + col0+1] = acc[mt][nt][1];
            Cg[(long)(row0+8)*D_INNER + col0  ] = acc[mt][nt][2];
            Cg[(long)(row0+8)*D_INNER + col0+1] = acc[mt][nt][3];
        }
    }
}

// states: C[p][n] = sum_l (xdt[l,p]*decay_l) * B[l,n]; decay folded in staging
__global__ __launch_bounds__(256)
void k_states3()
{
    __shared__ __half As[128][SS];
    __shared__ __half Bs[128][SS];
    __shared__ float cs[CHUNK];
    int z = blockIdx.x;
    ZIdx zi = zdec(z);
    long brow = (long)zi.b*SEQ + zi.c*CHUNK;
    int tid = threadIdx.x;
    int warp = tid >> 5, lane = tid & 31;
    int wm = warp >> 2, wn = warp & 3;
    int g = lane >> 2, t4 = lane & 3;

    const float* cum = g_dAcum + ((long)zi.b*N_HEADS + zi.h)*SEQ + zi.c*CHUNK;
    if (tid < CHUNK) cs[tid] = cum[tid];
    __syncthreads();
    float cum_last = cs[CHUNK-1];

    const __half* Ag = g_xdt_h + brow*D_INNER + zi.h*HEADDIM;   // [l][p]
    const __half* Bg = g_bc_h + brow*(2*D_STATE);               // [l][n] (B cols)

    float acc[4][4][4];
    #pragma unroll
    for (int i = 0; i < 4; i++)
        #pragma unroll
        for (int j = 0; j < 4; j++)
            #pragma unroll
            for (int q = 0; q < 4; q++) acc[i][j][q] = 0.f;

    for (int kt = 0; kt < CHUNK/32; kt++) {
        int k0 = kt * 32;
        // A: xdt transposed-stage with per-l decay multiply
        #pragma unroll
        for (int i = 0; i < 8; i++) {
            int idx = tid + i*256;
            int k = idx >> 6, m2 = (idx & 63) * 2;
            int l = k0 + k;
            float d = fexp(cum_last - cs[l]);
            __half2 v = *(const __half2*)&Ag[(long)l*D_INNER + m2];
            float2 f = __half22float2(v);
            As[m2  ][k] = __float2half_rn(f.x * d);
            As[m2+1][k] = __float2half_rn(f.y * d);
        }
        // B: plain B transposed-stage
        #pragma unroll
        for (int i = 0; i < 8; i++) {
            int idx = tid + i*256;
            int k = idx >> 6, n2 = (idx & 63) * 2;
            __half2 v = *(const __half2*)&Bg[(long)(k0+k)*(2*D_STATE) + n2];
            Bs[n2  ][k] = __low2half(v);
            Bs[n2+1][k] = __high2half(v);
        }
        __syncthreads();
        #pragma unroll
        for (int ks = 0; ks < 2; ks++) {
            int kb = ks * 16;
            uint32_t af[4][4], bf[4][2];
            #pragma unroll
            for (int mt = 0; mt < 4; mt++) {
                int r0 = wm*64 + mt*16 + g;
                af[mt][0] = *(const uint32_t*)&As[r0  ][kb + t4*2    ];
                af[mt][1] = *(const uint32_t*)&As[r0+8][kb + t4*2    ];
                af[mt][2] = *(const uint32_t*)&As[r0  ][kb + t4*2 + 8];
                af[mt][3] = *(const uint32_t*)&As[r0+8][kb + t4*2 + 8];
            }
            #pragma unroll
            for (int nt = 0; nt < 4; nt++) {
                int cc = wn*32 + nt*8 + g;
                bf[nt][0] = *(const uint32_t*)&Bs[cc][kb + t4*2    ];
                bf[nt][1] = *(const uint32_t*)&Bs[cc][kb + t4*2 + 8];
            }
            #pragma unroll
            for (int mt = 0; mt < 4; mt++)
                #pragma unroll
                for (int nt = 0; nt < 4; nt++)
                    MMA16(acc[mt][nt], af[mt], bf[nt]);
        }
        __syncthreads();
    }

    float* Cg = g_states + (long)z*HEADDIM*D_STATE;
    #pragma unroll
    for (int mt = 0; mt < 4; mt++) {
        int row0 = wm*64 + mt*16 + g;
        #pragma unroll
        for (int nt = 0; nt < 4; nt++) {
            int col0 = wn*32 + nt*8 + 2*t4;
            Cg[(long)row0*D_STATE + col0  ] = acc[mt][nt][0];
            Cg[(long)row0*D_STATE + col0+1] = acc[mt][nt][1];
            Cg[(long)(row0+8)*D_STATE + col0  ] = acc[mt][nt][2];
            Cg[(long)(row0+8)*D_STATE + col0+1] = acc[mt][nt][3];
        }
    }
}

// ---------------- prep kernels --------------------------------------------
__global__ __launch_bounds__(256)
void k_prep_lg()
{
    int z = blockIdx.x, lt = blockIdx.y;
    ZIdx zi = zdec(z);
    int bc = z / N_HEADS;
    const float* cum = g_dAcum + ((long)zi.b*N_HEADS + zi.h)*SEQ + zi.c*CHUNK;
    __shared__ float cs[CHUNK];
    if (threadIdx.x < CHUNK) cs[threadIdx.x] = cum[threadIdx.x];
    __syncthreads();
    const __half* G = g_G + (long)bc*CHUNK*CHUNK;
    __half* LG = g_LG + (long)z*CHUNK*CHUNK;
    int tid = threadIdx.x;
    #pragma unroll 4
    for (int j = 0; j < 64; j++) {
        int lin = tid + j*256;
        int l = lt*64 + (lin >> 8);
        int s = lin & 255;
        float v = 0.f;
        if (s <= l) v = __half2float(G[l*CHUNK + s]) * fexp(cs[l] - cs[s]);
        LG[l*CHUNK + s] = __float2half_rn(v);
    }
}

__global__ __launch_bounds__(256)
void k_tohalf(const float* __restrict__ src, __half* __restrict__ dst, long n2)
{
    long i = (long)blockIdx.x * 256 + threadIdx.x;
    long stride = (long)gridDim.x * 256;
    for (; i < n2; i += stride) {
        float2 v = *reinterpret_cast<const float2*>(src + i*2);
        *reinterpret_cast<__half2*>(dst + i*2) = __floats2half2_rn(v.x, v.y);
    }
}

// ---------------- exact fp32 dt projection + softplus ---------------------
__global__ __launch_bounds__(256)
void k_dtproj(const float* __restrict__ inputs,
              const float* __restrict__ in_proj_w,
              const float* __restrict__ in_proj_b,
              const float* __restrict__ dt_bias)
{
    __shared__ float xs[32][133];
    __shared__ float ws[32][133];
    int t = threadIdx.x;
    long r0 = (long)blockIdx.x * 32;
    int r = t >> 3;
    int hb = (t & 7) * 4;
    const float* Wdt = in_proj_w + (size_t)(D_INNER + CONV_DIM) * DIM;
    float acc[4] = {0.f, 0.f, 0.f, 0.f};
    for (int k0 = 0; k0 < DIM; k0 += 128) {
        #pragma unroll
        for (int i = 0; i < 4; i++) {
            int idx = t + i*256;
            int row = idx >> 5, c4 = (idx & 31) * 4;
            float4 v = *reinterpret_cast<const float4*>(&inputs[(r0+row)*DIM + k0 + c4]);
            xs[row][c4] = v.x; xs[row][c4+1] = v.y; xs[row][c4+2] = v.z; xs[row][c4+3] = v.w;
            float4 w = *reinterpret_cast<const float4*>(&Wdt[(size_t)row*DIM + k0 + c4]);
            ws[row][c4] = w.x; ws[row][c4+1] = w.y; ws[row][c4+2] = w.z; ws[row][c4+3] = w.w;
        }
        __syncthreads();
        #pragma unroll 8
        for (int k = 0; k < 128; k++) {
            float xv = xs[r][k];
            #pragma unroll
            for (int j = 0; j < 4; j++)
                acc[j] = fmaf(xv, ws[hb+j][k], acc[j]);
        }
        __syncthreads();
    }
    #pragma unroll
    for (int j = 0; j < 4; j++) {
        int h = hb + j;
        float x = acc[j] + in_proj_b[D_INNER + CONV_DIM + h] + dt_bias[h];
        g_dt[(r0 + r)*N_HEADS + h] = (x > 20.f) ? x : log1pf(expf(x));
    }
}

// ---------------- tiled conv + SiLU + fused xdt/bc fp16 -------------------
#define CTS 32
__global__ __launch_bounds__(256)
void k_conv_t(const float* __restrict__ conv_w, const float* __restrict__ conv_b)
{
    __shared__ float xs[CTS + 3][256];
    __shared__ float sdt[CTS][2];
    int tid = threadIdx.x;
    int c0 = blockIdx.x * 256;
    int s0 = blockIdx.y * CTS;
    int b  = blockIdx.z;
    int c  = c0 + tid;
    long base = ((long)b*SEQ + s0) * D_IN_PROJ + D_INNER + c;

    #pragma unroll
    for (int i = 0; i < CTS + 3; i++) {
        int sp = s0 - 3 + i;
        xs[i][tid] = (sp >= 0) ? g_zxbcdt[base + (long)(i - 3) * D_IN_PROJ] : 0.f;
    }
    bool isx = (c0 < D_INNER);
    if (isx && tid < CTS*2) {
        int j = tid >> 1, hh = tid & 1;
        sdt[j][hh] = g_dt[((long)b*SEQ + s0 + j)*N_HEADS + (c0 >> 7) + hh];
    }
    __syncthreads();

    float w0 = conv_w[c*D_CONV+0], w1 = conv_w[c*D_CONV+1];
    float w2 = conv_w[c*D_CONV+2], w3 = conv_w[c*D_CONV+3];
    float bsv = conv_b[c];
    int hsel = (tid >> 7) & 1;

    #pragma unroll 4
    for (int j = 0; j < CTS; j++) {
        float acc = bsv;
        acc = fmaf(xs[j  ][tid], w0, acc);
        acc = fmaf(xs[j+1][tid], w1, acc);
        acc = fmaf(xs[j+2][tid], w2, acc);
        acc = fmaf(xs[j+3][tid], w3, acc);
        float v = acc / (1.f + expf(-acc));
        long bs = (long)b*SEQ + s0 + j;
        g_xBC[bs*CONV_DIM + c] = v;
        if (isx) {
            g_xdt_h[bs*D_INNER + c] = __float2half_rn(v * sdt[j][hsel]);
        } else {
            int cc = c - D_INNER;
            if (cc >= 0)
                g_bc_h[bs*(2*D_STATE) + cc] = __float2half_rn(v);
        }
    }
}

// ---------------- chunk-local inclusive cumsum of A*dt --------------------
__global__ __launch_bounds__(CHUNK)
void k_cumsum(const float* __restrict__ A_log)
{
    int bz = blockIdx.x;
    int c = bz % NCHUNK; int bh = bz / NCHUNK;
    int h = bh % N_HEADS; int b = bh / N_HEADS;
    int l = threadIdx.x;
    int sg = c*CHUNK + l;
    float A = -expf(A_log[h]);
    float val = A * g_dt[((long)b*SEQ + sg)*N_HEADS + h];
    __shared__ float buf[CHUNK];
    buf[l] = val; __syncthreads();
    for (int off = 1; off < CHUNK; off <<= 1) {
        float t = (l >= off) ? buf[l-off] : 0.f;
        __syncthreads();
        buf[l] += t;
        __syncthreads();
    }
    g_dAcum[((long)b*N_HEADS + h)*SEQ + sg] = buf[l];
}

// ---------------- inter-chunk recurrence (-> Sin fp16), full-chip ---------
__global__ __launch_bounds__(256)
void k_chunkrec()
{
    int bh = blockIdx.x;
    int h = bh % N_HEADS; int b = bh / N_HEADS;
    const float* cum = g_dAcum + (long)bh*SEQ;
    float csum[NCHUNK];
    #pragma unroll
    for (int c = 0; c < NCHUNK; c++) csum[c] = expf(cum[c*CHUNK + CHUNK-1]);
    int pn0 = blockIdx.y * (HEADDIM*D_STATE/8);
    #pragma unroll
    for (int j = 0; j < (HEADDIM*D_STATE/8)/256; j++) {
        int pn = pn0 + j*256 + threadIdx.x;
        float carry = 0.f;
        #pragma unroll
        for (int c = 0; c < NCHUNK; c++) {
            long z = ((long)b*NCHUNK + c)*N_HEADS + h;
            long idx = z*HEADDIM*D_STATE + pn;
            g_sin_h[idx] = __float2half_rn(carry);
            carry = carry * csum[c] + g_states[idx];
        }
    }
}

// ---------------- gate (y + D*x) * silu(z) + RMSNorm -> fp16 --------------
__global__ __launch_bounds__(256)
void k_gatenorm(const float* __restrict__ norm_w, const float* __restrict__ Dv)
{
    long row = blockIdx.x;
    const float* zrow = g_zxbcdt + row*D_IN_PROJ;
    const float* xrow = g_xBC + row*CONV_DIM;
    float* yrow = g_y + row*D_INNER;
    __half* yh = g_y_h + row*D_INNER;
    float vals[16];
    float local = 0.f;
    #pragma unroll
    for (int i = 0; i < 16; i++) {
        int d = threadIdx.x + i*256;
        float z = zrow[d];
        float v = (yrow[d] + Dv[d >> 7] * xrow[d]) * (z / (1.f + expf(-z)));
        vals[i] = v;
        local += v * v;
    }
    __shared__ float red[256];
    red[threadIdx.x] = local; __syncthreads();
    for (int off = 128; off > 0; off >>= 1) {
        if (threadIdx.x < off) red[threadIdx.x] += red[threadIdx.x + off];
        __syncthreads();
    }
    float scale = rsqrtf(red[0] / D_INNER + EPS);
    #pragma unroll
    for (int i = 0; i < 16; i++) {
        int d = threadIdx.x + i*256;
        yh[d] = __float2half_rn(vals[i] * scale * norm_w[d]);
    }
}

// --------------------------------------------------------------------------
extern "C" void kernel_launch(void* const* d_in, const int* in_sizes, int n_in,
                              void* d_out, int out_size)
{
    const float* inputs     = (const float*)d_in[0];
    const float* in_proj_w  = (const float*)d_in[1];
    const float* in_proj_b  = (const float*)d_in[2];
    const float* out_proj_w = (const float*)d_in[3];
    const float* out_proj_b = (const float*)d_in[4];
    const float* conv_w     = (const float*)d_in[5];
    const float* conv_b     = (const float*)d_in[6];
    const float* dt_bias    = (const float*)d_in[7];
    const float* A_log      = (const float*)d_in[8];
    const float* Dv         = (const float*)d_in[9];
    const float* norm_w     = (const float*)d_in[10];
    float* out = (float*)d_out;

    float *zx;
    __half *Gp, *inh, *winh, *wouth, *yh, *bch;
    cudaGetSymbolAddress((void**)&zx,    g_zxbcdt);
    cudaGetSymbolAddress((void**)&Gp,    g_G);
    cudaGetSymbolAddress((void**)&inh,   g_in_h);
    cudaGetSymbolAddress((void**)&winh,  g_win_h);
    cudaGetSymbolAddress((void**)&wouth, g_wout_h);
    cudaGetSymbolAddress((void**)&yh,    g_y_h);
    cudaGetSymbolAddress((void**)&bch,   g_bc_h);

    cudaFuncSetAttribute(gemm_h,  cudaFuncAttributeMaxDynamicSharedMemorySize, GSMEM);
    cudaFuncSetAttribute(gemm_hh, cudaFuncAttributeMaxDynamicSharedMemorySize, GSMEM);

    const int M = BATCH * SEQ;     // 4096

    // 0) fp16 mirrors
    k_tohalf<<<2048, 256>>>(inputs,     inh,   (long)M*DIM/2);
    k_tohalf<<<2048, 256>>>(in_proj_w,  winh,  (long)D_IN_PROJ*DIM/2);
    k_tohalf<<<2048, 256>>>(out_proj_w, wouth, (long)DIM*D_INNER/2);

    // 1) in_proj
    {
        dim3 grid((D_IN_PROJ + 127)/128, M/128, 1);
        gemm_h<<<grid, 256, GSMEM>>>(inh, DIM, 0, winh, DIM, 0,
                              zx, D_IN_PROJ, 0, M, D_IN_PROJ, DIM, in_proj_b);
    }
    // 2) exact dt projection (before conv: conv consumes dt)
    k_dtproj<<<M/32, 256>>>(inputs, in_proj_w, in_proj_b, dt_bias);
    // 3) tiled conv + silu, fused xdt/bc fp16 production
    {
        dim3 grid(CONV_DIM/256, SEQ/CTS, BATCH);
        k_conv_t<<<grid, 256>>>(conv_w, conv_b);
    }
    // 4) cumsum
    k_cumsum<<<BATCH*N_HEADS*NCHUNK, CHUNK>>>(A_log);
    // 5) G = C @ B^T per (b,c), fp16 output
    {
        dim3 grid(CHUNK/128, CHUNK/128, BATCH*NCHUNK);
        gemm_hh<<<grid, 256, GSMEM>>>(bch + D_STATE, 2*D_STATE, (long)CHUNK*2*D_STATE,
                              bch,           2*D_STATE, (long)CHUNK*2*D_STATE,
                              Gp, CHUNK, (long)CHUNK*CHUNK,
                              CHUNK, CHUNK, D_STATE);
    }
    // 6) LG prep (only remaining prep)
    {
        dim3 grid(NBCH, CHUNK/64);
        k_prep_lg<<<grid, 256>>>();
    }
    // 7) states with decay folded in staging (no Bdec buffer)
    k_states3<<<NBCH, 256>>>();
    // 8) inter-chunk recurrence -> Sin fp16 (full-chip)
    {
        dim3 grid(BATCH*N_HEADS, 8);
        k_chunkrec<<<grid, 256>>>();
    }
    // 9) fused Y_diag + scaled Y_off (tensor), single g_y store
    {
        dim3 grid(NBCH, CHUNK/128);
        k_ydiagoff<<<grid, 256>>>();
    }
    // 10) gate + D*x + RMSNorm -> fp16
    k_gatenorm<<<BATCH*SEQ, 256>>>(norm_w, Dv);
    // 11) out_proj
    {
        dim3 grid(DIM/128, M/128, 1);
        gemm_h<<<grid, 256, GSMEM>>>(yh, D_INNER, 0, wouth, D_INNER, 0,
                              out, DIM, 0, M, DIM, D_INNER, out_proj_b);
    }
}